// round 10
// baseline (speedup 1.0000x reference)
#include <cuda_runtime.h>
#include <cuda_bf16.h>
#include <math.h>

// ---------------------------------------------------------------------------
// Problem constants
// ---------------------------------------------------------------------------
#define BATCH 128
#define E_DIM 128
#define NHEAD 8
#define HW 256
#define MEM 8
#define DDIM 4096
#define BH 1024

#define OFF_H  ((size_t)0)
#define OFF_C  ((size_t)4194304)
#define OFF_K  ((size_t)8388608)
#define OFF_V  ((size_t)41943040)

typedef unsigned int u32;

// padded B image geometry: 18x18 rows x 64 ch bf16 = 324 rows x 128 B
#define BPAD_ROWS 324
#define BPAD_BYTES (BPAD_ROWS * 128)          // 41472 per plane (hi or lo)
#define BKC_BYTES  (2 * BPAD_BYTES)           // 82944 per kc (hi + lo)

// ---------------------------------------------------------------------------
// Scratch (device globals — allocation-free; zero-initialized at load, so
// never-written border rows of the padded images stay zero forever)
// ---------------------------------------------------------------------------
__device__ float g_cc  [(size_t)BATCH * 640 * HW];
__device__ float g_q   [(size_t)BH * DDIM];
__device__ float g_outp[(size_t)BATCH * E_DIM * HW];

// padded bf16 hi/lo input images: [b][kc(4)][hi/lo][41472 B]
__device__ __nv_bfloat16 g_bin  [(size_t)BATCH * 4 * 2 * 20736];
// padded bf16 hi/lo attention-output images: [b][kc(2)][hi/lo][41472 B]
__device__ __nv_bfloat16 g_battn[(size_t)BATCH * 2 * 2 * 20736];

// Pre-swizzled bf16 A tiles (hi/lo). tile = (mtile*9 + tap)*KC + kc,
// each = 64 oc rows x 64 k, K-major, SW128 swizzle -> 8192 bytes.
__device__ __nv_bfloat16 g_wm_hi[360 * 4096], g_wm_lo[360 * 4096];
__device__ __nv_bfloat16 g_wp_hi[108 * 4096], g_wp_lo[108 * 4096];
__device__ __nv_bfloat16 g_wo_hi[ 36 * 4096], g_wo_lo[ 36 * 4096];

__device__ __forceinline__ float sigmoidf_(float x) { return 1.0f / (1.0f + expf(-x)); }

#define SW128(o) ((o) ^ (((o) >> 3) & 0x70))

__device__ __forceinline__ u32 smem_u32(const void* p) {
    u32 a;
    asm("{ .reg .u64 t; cvta.to.shared.u64 t, %1; cvt.u32.u64 %0, t; }" : "=r"(a) : "l"(p));
    return a;
}

__device__ __forceinline__ void ldm_x4(u32* r, u32 addr) {
    asm volatile("ldmatrix.sync.aligned.m8n8.x4.shared.b16 {%0,%1,%2,%3}, [%4];"
        : "=r"(r[0]), "=r"(r[1]), "=r"(r[2]), "=r"(r[3]) : "r"(addr));
}

__device__ __forceinline__ void mma_bf16(float* c, const u32* a, u32 b0, u32 b1) {
    asm volatile("mma.sync.aligned.m16n8k16.row.col.f32.bf16.bf16.f32 "
        "{%0,%1,%2,%3}, {%4,%5,%6,%7}, {%8,%9}, {%0,%1,%2,%3};"
        : "+f"(c[0]), "+f"(c[1]), "+f"(c[2]), "+f"(c[3])
        : "r"(a[0]), "r"(a[1]), "r"(a[2]), "r"(a[3]), "r"(b0), "r"(b1));
}

__device__ __forceinline__ void cp16(u32 dst, const void* src) {
    asm volatile("cp.async.cg.shared.global [%0], [%1], 16;"
                 :: "r"(dst), "l"(src) : "memory");
}
#define CP_COMMIT() asm volatile("cp.async.commit_group;" ::: "memory")
#define CP_WAIT0()  asm volatile("cp.async.wait_group 0;"  ::: "memory")

// hi/lo split of two floats into packed bf16x2 words
__device__ __forceinline__ void split2(float a, float c, u32& ph, u32& pl) {
    const __nv_bfloat16 ha = __float2bfloat16(a), hc = __float2bfloat16(c);
    const __nv_bfloat16 la = __float2bfloat16(a - __bfloat162float(ha));
    const __nv_bfloat16 lc = __float2bfloat16(c - __bfloat162float(hc));
    const __nv_bfloat162 hh = __halves2bfloat162(ha, hc);
    const __nv_bfloat162 ll = __halves2bfloat162(la, lc);
    ph = *(const u32*)&hh; pl = *(const u32*)&ll;
}

// ---------------------------------------------------------------------------
// Stream/event resources (static init — allocation-free in kernel_launch)
// ---------------------------------------------------------------------------
struct OverlapRes {
    cudaStream_t sB;
    cudaEvent_t  evFork, evJoin;
    OverlapRes() {
        cudaStreamCreateWithFlags(&sB, cudaStreamNonBlocking);
        cudaEventCreateWithFlags(&evFork, cudaEventDisableTiming);
        cudaEventCreateWithFlags(&evJoin, cudaEventDisableTiming);
    }
};
static OverlapRes g_res;

// ---------------------------------------------------------------------------
// Input prep: fp32 (input | h_cur) -> padded bf16 hi/lo images in gmem.
// block = (kc, b); thread = pixel. Interior rows only (borders stay zero-init).
// ---------------------------------------------------------------------------
__global__ void __launch_bounds__(256)
prep_in(const float* __restrict__ input, const float* __restrict__ h_cur)
{
    const int kc = blockIdx.x, b = blockIdx.y;
    const int tid = threadIdx.x;
    const float* cb = (kc < 2) ? input + ((size_t)b * 128 + kc * 64) * 256
                               : h_cur + ((size_t)b * 128 + (kc - 2) * 64) * 256;
    char* dhi = (char*)g_bin + (size_t)(b * 4 + kc) * BKC_BYTES;
    char* dlo = dhi + BPAD_BYTES;

    const int padw = ((tid >> 4) + 1) * 18 + (tid & 15) + 1;
    const u32 rowb = (u32)(padw * 128);
    const u32 rswz = (u32)((padw & 7) << 4);
#pragma unroll
    for (int gg = 0; gg < 8; gg++) {
        float v[8];
#pragma unroll
        for (int j = 0; j < 8; j++)
            v[j] = __ldg(cb + (size_t)(gg * 8 + j) * 256 + tid);
        u32 ph[4], pl[4];
#pragma unroll
        for (int j = 0; j < 4; j++) split2(v[2*j], v[2*j+1], ph[j], pl[j]);
        const u32 o = rowb + ((u32)(gg * 16) ^ rswz);
        *(uint4*)(dhi + o) = make_uint4(ph[0], ph[1], ph[2], ph[3]);
        *(uint4*)(dlo + o) = make_uint4(pl[0], pl[1], pl[2], pl[3]);
    }
}

// ---------------------------------------------------------------------------
// Weight prep: fp32 [oc][CIN][9] -> swizzled bf16 hi/lo 64x64 K-major tiles
// ---------------------------------------------------------------------------
template<int WSEL>
__global__ void __launch_bounds__(256)
prep_w(const float* __restrict__ w, int ntiles, int KC)
{
    const int idx = blockIdx.x * 256 + threadIdx.x;
    if (idx >= ntiles * 2048) return;
    const int tile = idx >> 11, r = idx & 2047, row = r >> 5, kp = r & 31;
    const int kc = tile % KC, t2 = tile / KC, tap = t2 % 9, mtile = t2 / 9;
    const int CIN = KC * 64;
    const int oc  = mtile * 64 + row;
    const int cin = kc * 64 + kp * 2;
    const size_t wb = ((size_t)oc * CIN + cin) * 9 + tap;
    u32 ph, pl;
    split2(w[wb], w[wb + 9], ph, pl);
    const u32 off = SW128((u32)(row * 128 + kp * 4));
    __nv_bfloat16* hi = (WSEL == 0) ? g_wm_hi : (WSEL == 1) ? g_wp_hi : g_wo_hi;
    __nv_bfloat16* lo = (WSEL == 0) ? g_wm_lo : (WSEL == 1) ? g_wp_lo : g_wo_lo;
    *(u32*)((char*)hi + (size_t)tile * 8192 + off) = ph;
    *(u32*)((char*)lo + (size_t)tile * 8192 + off) = pl;
}

// ---------------------------------------------------------------------------
// Epilogue store of a float2 (two px) for one output channel
// ---------------------------------------------------------------------------
template<int OUTSEL>
__device__ __forceinline__ void store2(int ocg, int px, float v0, float v1, int b,
                                       const float* __restrict__ resid,
                                       const float* __restrict__ pos_w,
                                       float* __restrict__ d_out)
{
    if (OUTSEL == 0) {
        *(float2*)(g_cc + ((size_t)b * 640 + ocg) * 256 + px) = make_float2(v0, v1);
    } else if (OUTSEL == 2) {
        const float2 r = *(const float2*)(resid + ((size_t)b * 128 + ocg) * 256 + px);
        *(float2*)(g_outp + ((size_t)b * 128 + ocg) * 256 + px) =
            make_float2(v0 + r.x, v1 + r.y);
    } else {
        const int h = ocg / 48, rr = ocg % 48, grp = rr / 16, c = rr % 16;
        const size_t bh = (size_t)b * 8 + h;
        const size_t d0 = (size_t)c * 256 + px;
        if (grp == 0) {
            const float2 pw = *(const float2*)(pos_w + (size_t)7 * 32768 + (size_t)h * 4096 + d0);
            *(float2*)(d_out + OFF_K + (bh * 8 + 7) * 4096 + d0) =
                make_float2(v0 + pw.x, v1 + pw.y);
        } else if (grp == 1) {
            *(float2*)(g_q + bh * 4096 + d0) = make_float2(v0 * 0.015625f, v1 * 0.015625f);
        } else {
            *(float2*)(d_out + OFF_V + (bh * 8 + 7) * 4096 + d0) = make_float2(v0, v1);
        }
    }
}

// ---------------------------------------------------------------------------
// Implicit-GEMM 3x3 conv, mma.sync bf16x3, padded-B shift trick.
// B now arrives pre-converted from gmem via cp.async (no in-kernel cvt).
// 256 threads / 64-oc CTA, 2 CTAs/SM. warps: 2(M) x 4(N).
// SMEM: A0_hi/lo[0,16K) A1_hi/lo[16K,32K) B_hi[32768) B_lo[74240) -> 115712
// ---------------------------------------------------------------------------
#define SB_HI 32768
#define SB_LO (32768 + BPAD_BYTES)            // 74240
#define CONV_SMEM (SB_LO + BPAD_BYTES)        // 115712

template<int KC, int OUTSEL>
__global__ void __launch_bounds__(256, 2)
conv_mma(const __nv_bfloat16* __restrict__ whi, const __nv_bfloat16* __restrict__ wlo,
         const char* __restrict__ ball, int bkc,
         const float* __restrict__ bias, const float* __restrict__ resid,
         const float* __restrict__ pos_w, float* __restrict__ d_out)
{
    extern __shared__ char smem[];
    const int b     = blockIdx.y;
    const int mtile = blockIdx.x;
    const int tid   = threadIdx.x;
    const int wid   = tid >> 5;
    const int lane  = tid & 31;
    const u32 sbase = smem_u32(smem);

    const char* bimg = ball + (size_t)b * bkc * BKC_BYTES;

    const int mrow  = (wid & 1) * 32;
    const int nbase = (wid >> 1) * 64;

    const int sel = lane >> 3, r8 = lane & 7;
    const int ar0  = mrow + r8 + ((sel & 1) << 3);
    const int ar1  = ar0 + 16;
    const u32 akad = (u32)((sel >> 1) << 4);
    const u32 ao0b = (u32)(ar0 * 128);
    const u32 ao1b = (u32)(ar1 * 128);
    const u32 asz0 = (u32)((ar0 & 7) << 4);
    const u32 asz1 = (u32)((ar1 & 7) << 4);
    const int pxr  = nbase + r8 + ((sel >> 1) << 3);
    const u32 bkad = (u32)((sel & 1) << 4);
    const int pad00 = ((pxr >> 4) + 1) * 18 + ((pxr & 15) + 1);

    float acc0[32], acc1[32];
#pragma unroll
    for (int i = 0; i < 32; i++) { acc0[i] = 0.0f; acc1[i] = 0.0f; }

    auto issueA = [&](int tile, int buf) {
        const char* gh = (const char*)whi + (size_t)tile * 8192;
        const char* gl = (const char*)wlo + (size_t)tile * 8192;
        const u32 dh = sbase + (u32)(buf << 14);
        const u32 dl = dh + 8192;
#pragma unroll
        for (int r = 0; r < 2; r++) {
            const u32 o = (u32)(tid * 16 + r * 4096);
            cp16(dh + o, gh + o);
            cp16(dl + o, gl + o);
        }
        CP_COMMIT();
    };
    auto issueB = [&](int kc) {
        const char* sh = bimg + (size_t)kc * BKC_BYTES;
        for (u32 o = (u32)tid * 16; o < BPAD_BYTES; o += 4096) {
            cp16(sbase + SB_HI + o, sh + o);
            cp16(sbase + SB_LO + o, sh + BPAD_BYTES + o);
        }
        CP_COMMIT();
    };

    // prologue: prefetch A(kc0,tap0) and B(kc0)
    issueA((mtile * 9) * KC, 0);
    issueB(0);

    int g = 0;
    for (int kc = 0; kc < KC; kc++) {
        if (kc > 0) {
            __syncthreads();      // all warps done reading B of kc-1
            issueB(kc);
        }
        for (int tap = 0; tap < 9; tap++) {
            const int s = g & 1;
            CP_WAIT0();
            __syncthreads();      // A[s] (and B at tap 0) visible; buf s^1 free

            {
                int ntap = tap + 1, nkc = kc;
                if (ntap == 9) { ntap = 0; nkc = kc + 1; }
                if (nkc < KC)
                    issueA((mtile * 9 + ntap) * KC + nkc, s ^ 1);
            }

            const int toff = (tap / 3 - 1) * 18 + (tap % 3 - 1);
            const u32 Ab = sbase + (u32)(s << 14);
#pragma unroll
            for (int q = 0; q < 4; q++) {
                const u32 ka = (u32)(q * 32) + akad;
                u32 a0h[4], a0l[4], a1h[4], a1l[4];
                const u32 o0 = ao0b + (ka ^ asz0);
                const u32 o1 = ao1b + (ka ^ asz1);
                ldm_x4(a0h, Ab + o0);
                ldm_x4(a0l, Ab + 8192 + o0);
                ldm_x4(a1h, Ab + o1);
                ldm_x4(a1l, Ab + 8192 + o1);
                const u32 kb = (u32)(q * 32) + bkad;
#pragma unroll
                for (int jj = 0; jj < 4; jj++) {
                    const int pr = pad00 + jj * 18 + toff;
                    const u32 bo = (u32)(pr * 128) + (kb ^ ((u32)(pr & 7) << 4));
                    u32 bh[4], bl[4];
                    ldm_x4(bh, sbase + SB_HI + bo);
                    ldm_x4(bl, sbase + SB_LO + bo);
                    float* c0 = acc0 + jj * 8;
                    mma_bf16(c0,     a0h, bh[0], bh[1]);  mma_bf16(c0 + 4, a0h, bh[2], bh[3]);
                    mma_bf16(c0,     a0h, bl[0], bl[1]);  mma_bf16(c0 + 4, a0h, bl[2], bl[3]);
                    mma_bf16(c0,     a0l, bh[0], bh[1]);  mma_bf16(c0 + 4, a0l, bh[2], bh[3]);
                    float* c1 = acc1 + jj * 8;
                    mma_bf16(c1,     a1h, bh[0], bh[1]);  mma_bf16(c1 + 4, a1h, bh[2], bh[3]);
                    mma_bf16(c1,     a1h, bl[0], bl[1]);  mma_bf16(c1 + 4, a1h, bl[2], bl[3]);
                    mma_bf16(c1,     a1l, bh[0], bh[1]);  mma_bf16(c1 + 4, a1l, bh[2], bh[3]);
                }
            }
            g++;
        }
    }

    const int g2 = lane >> 2, qp = lane & 3;
#pragma unroll
    for (int mt = 0; mt < 2; mt++) {
        const float* am = mt ? acc1 : acc0;
        const int ocg0 = mtile * 64 + mrow + mt * 16 + g2;
        const int ocg1 = ocg0 + 8;
        const float bv0 = __ldg(bias + ocg0);
        const float bv1 = __ldg(bias + ocg1);
#pragma unroll
        for (int t = 0; t < 8; t++) {
            const int px = nbase + t * 8 + qp * 2;
            const float* c = am + t * 4;
            store2<OUTSEL>(ocg0, px, c[0] + bv0, c[1] + bv0, b, resid, pos_w, d_out);
            store2<OUTSEL>(ocg1, px, c[2] + bv1, c[3] + bv1, b, resid, pos_w, d_out);
        }
    }
}

// ---------------------------------------------------------------------------
// LSTM gate fusion
// ---------------------------------------------------------------------------
__global__ void __launch_bounds__(256)
gates_kernel(const float* __restrict__ c_cur, float* __restrict__ d_out)
{
    const size_t idx = (size_t)blockIdx.x * 256 + threadIdx.x;
    if (idx >= (size_t)BATCH * E_DIM * HW) return;
    const int b = (int)(idx >> 15);
    const int r = (int)(idx & 32767);
    const size_t base = (size_t)b * 640 * HW;
    const float ci = g_cc[base + r];
    const float cf = g_cc[base + (size_t)128 * HW + r];
    const float cg = g_cc[base + (size_t)384 * HW + r];
    d_out[OFF_C + idx] = sigmoidf_(cf) * c_cur[idx] + sigmoidf_(ci) * tanhf(cg);
}

// ---------------------------------------------------------------------------
// Fused attention; output written directly as padded bf16 hi/lo images
// ---------------------------------------------------------------------------
__global__ void __launch_bounds__(256)
attn_fused(const float* __restrict__ concat_k, const float* __restrict__ concat_v,
           const unsigned int* __restrict__ mask,
           const float* __restrict__ pos_w, const float* __restrict__ pos_b,
           float* __restrict__ ret_k, float* __restrict__ ret_v)
{
    const int bh  = blockIdx.x;
    const int h   = bh & 7;
    const int tid = threadIdx.x;
    const int wid = tid >> 5, lane = tid & 31;

    float qreg[16];
#pragma unroll
    for (int i = 0; i < 16; i++)
        qreg[i] = g_q[(size_t)bh * DDIM + i * 256 + tid];

    __shared__ float red2[8][MEM];
    __shared__ float w8[MEM];

    float part[MEM];
#pragma unroll
    for (int m = 0; m < MEM; m++) part[m] = 0.0f;

#pragma unroll
    for (int m = 0; m < MEM; m++) {
        const float* ks = (m < 7)
            ? concat_k + ((size_t)bh * MEM + (m + 1)) * DDIM
            : ret_k    + ((size_t)bh * MEM + 7) * DDIM;
        const float* pw = pos_w + (size_t)m * 32768 + (size_t)h * DDIM;
        float p = 0.0f;
#pragma unroll
        for (int i = 0; i < 16; i++) {
            const int idx = i * 256 + tid;
            float kv = ks[idx];
            if (m < 7) {
                kv += pw[idx];
                ret_k[((size_t)bh * MEM + m) * DDIM + idx] = kv;
            }
            p = fmaf(qreg[i], kv, p);
        }
        part[m] = p;
    }

#pragma unroll
    for (int m = 0; m < MEM; m++)
#pragma unroll
        for (int off = 16; off > 0; off >>= 1)
            part[m] += __shfl_down_sync(0xffffffffu, part[m], off);
    if (lane == 0)
#pragma unroll
        for (int m = 0; m < MEM; m++) red2[wid][m] = part[m];
    __syncthreads();

    if (tid == 0) {
        float sc[MEM];
        float mx = -1e30f;
#pragma unroll
        for (int m = 0; m < MEM; m++) {
            float t = 0.0f;
#pragma unroll
            for (int w = 0; w < 8; w++) t += red2[w][m];
            float mf = (m == 7) ? 3.0f : (mask[bh * MEM + m] != 0u ? -1e30f : 0.0f);
            sc[m] = mf + t + pos_b[m * NHEAD + h];
            mx = fmaxf(mx, sc[m]);
        }
        float ssum = 0.0f;
#pragma unroll
        for (int m = 0; m < MEM; m++) { sc[m] = expf(sc[m] - mx); ssum += sc[m]; }
        const float inv = 1.0f / ssum;
#pragma unroll
        for (int m = 0; m < MEM; m++) w8[m] = sc[m] * inv;
    }
    __syncthreads();

    float wl[MEM];
#pragma unroll
    for (int m = 0; m < MEM; m++) wl[m] = w8[m];

    float accv[16];
#pragma unroll
    for (int i = 0; i < 16; i++) {
        const int idx = i * 256 + tid;
        float acc = 0.0f;
#pragma unroll
        for (int m = 0; m < MEM; m++) {
            float vv;
            if (m < 7) {
                vv = concat_v[((size_t)bh * MEM + (m + 1)) * DDIM + idx];
                ret_v[((size_t)bh * MEM + m) * DDIM + idx] = vv;
            } else {
                vv = ret_v[((size_t)bh * MEM + 7) * DDIM + idx];
            }
            acc = fmaf(wl[m], vv, acc);
        }
        accv[i] = acc;
    }

    // ---- write padded bf16 hi/lo image for the out conv ----
    u32 ph[8], pl[8];
#pragma unroll
    for (int j = 0; j < 8; j++) split2(accv[2*j], accv[2*j+1], ph[j], pl[j]);
    const int b  = bh >> 3;
    const int kc = h >> 2;
    char* dhi = (char*)g_battn + (size_t)(b * 2 + kc) * BKC_BYTES;
    char* dlo = dhi + BPAD_BYTES;
    const int padw = ((tid >> 4) + 1) * 18 + (tid & 15) + 1;
    const u32 rowb = (u32)(padw * 128);
    const u32 rswz = (u32)((padw & 7) << 4);
    const u32 coff = (u32)((h & 3) * 32);
    const u32 o0 = rowb + ((coff +  0) ^ rswz);
    const u32 o1 = rowb + ((coff + 16) ^ rswz);
    *(uint4*)(dhi + o0) = make_uint4(ph[0], ph[1], ph[2], ph[3]);
    *(uint4*)(dhi + o1) = make_uint4(ph[4], ph[5], ph[6], ph[7]);
    *(uint4*)(dlo + o0) = make_uint4(pl[0], pl[1], pl[2], pl[3]);
    *(uint4*)(dlo + o1) = make_uint4(pl[4], pl[5], pl[6], pl[7]);
}

// ---------------------------------------------------------------------------
// Fused LayerNorm + final LSTM update
// ---------------------------------------------------------------------------
__global__ void __launch_bounds__(512)
ln_final(const float* __restrict__ norm_w, const float* __restrict__ norm_b,
         float* __restrict__ d_out)
{
    const int b   = blockIdx.x;
    const int tid = threadIdx.x;
    const float* p = g_outp + (size_t)b * 32768;

    float s = 0.0f, s2 = 0.0f;
    for (int i = tid; i < 32768; i += 512) {
        const float v = p[i];
        s += v; s2 = fmaf(v, v, s2);
    }
#pragma unroll
    for (int off = 16; off > 0; off >>= 1) {
        s  += __shfl_down_sync(0xffffffffu, s, off);
        s2 += __shfl_down_sync(0xffffffffu, s2, off);
    }
    __shared__ float rs_[16], rs2_[16];
    __shared__ float sh_mu, sh_rs;
    if ((tid & 31) == 0) { rs_[tid >> 5] = s; rs2_[tid >> 5] = s2; }
    __syncthreads();
    if (tid == 0) {
        float ts = 0.0f, ts2 = 0.0f;
#pragma unroll
        for (int w = 0; w < 16; w++) { ts += rs_[w]; ts2 += rs2_[w]; }
        const float mu  = ts * (1.0f / 32768.0f);
        const float var = ts2 * (1.0f / 32768.0f) - mu * mu;
        sh_mu = mu;
        sh_rs = rsqrtf(var + 1e-5f);
    }
    __syncthreads();

    const float mu = sh_mu, rs = sh_rs;
    const size_t cbase = (size_t)b * 640 * HW;
    for (int i = tid; i < 32768; i += 512) {
        const float ln = (p[i] - mu) * rs * norm_w[i] + norm_b[i];
        const float o  = sigmoidf_(g_cc[cbase + (size_t)256 * HW + i]);
        const float a  = sigmoidf_(g_cc[cbase + (size_t)512 * HW + i]);
        const size_t idx = (size_t)b * 32768 + i;
        const float c = d_out[OFF_C + idx] + a * tanhf(ln);
        d_out[OFF_C + idx] = c;
        d_out[OFF_H + idx] = o * tanhf(c);
    }
}

// ---------------------------------------------------------------------------
// Launch — prep_in first (shared), then two-stream fork/join
// ---------------------------------------------------------------------------
extern "C" void kernel_launch(void* const* d_in, const int* in_sizes, int n_in,
                              void* d_out_v, int out_size)
{
    const float* input    = (const float*)d_in[0];
    const float* h_cur    = (const float*)d_in[1];
    const float* c_cur    = (const float*)d_in[2];
    const float* concat_k = (const float*)d_in[3];
    const float* concat_v = (const float*)d_in[4];
    const unsigned int* attn_mask = (const unsigned int*)d_in[5];
    const float* main_w   = (const float*)d_in[6];
    const float* main_b   = (const float*)d_in[7];
    const float* proj_w   = (const float*)d_in[8];
    const float* proj_b   = (const float*)d_in[9];
    const float* out_w    = (const float*)d_in[10];
    const float* out_b    = (const float*)d_in[11];
    const float* norm_w   = (const float*)d_in[12];
    const float* norm_b   = (const float*)d_in[13];
    const float* pos_w    = (const float*)d_in[14];
    const float* pos_b    = (const float*)d_in[15];
    float* d_out = (float*)d_out_v;

    cudaFuncSetAttribute(conv_mma<4,0>, cudaFuncAttributeMaxDynamicSharedMemorySize, CONV_SMEM);
    cudaFuncSetAttribute(conv_mma<2,1>, cudaFuncAttributeMaxDynamicSharedMemorySize, CONV_SMEM);
    cudaFuncSetAttribute(conv_mma<2,2>, cudaFuncAttributeMaxDynamicSharedMemorySize, CONV_SMEM);

    __nv_bfloat16 *wm_hi, *wm_lo, *wp_hi, *wp_lo, *wo_hi, *wo_lo;
    char *bin_p, *battn_p;
    cudaGetSymbolAddress((void**)&wm_hi, g_wm_hi);
    cudaGetSymbolAddress((void**)&wm_lo, g_wm_lo);
    cudaGetSymbolAddress((void**)&wp_hi, g_wp_hi);
    cudaGetSymbolAddress((void**)&wp_lo, g_wp_lo);
    cudaGetSymbolAddress((void**)&wo_hi, g_wo_hi);
    cudaGetSymbolAddress((void**)&wo_lo, g_wo_lo);
    cudaGetSymbolAddress((void**)&bin_p, g_bin);
    cudaGetSymbolAddress((void**)&battn_p, g_battn);

    cudaStream_t s0 = 0;
    cudaStream_t sB = g_res.sB;

    // ---- shared input prep (needed by main + proj) ----
    prep_in<<<dim3(4, BATCH), 256, 0, s0>>>(input, h_cur);

    // ---- fork ----
    cudaEventRecord(g_res.evFork, s0);
    cudaStreamWaitEvent(sB, g_res.evFork, 0);

    // ---- chain B (sB): proj weights+conv -> attn -> out conv ----
    prep_w<1><<<(108 * 2048) / 256, 256, 0, sB>>>(proj_w, 108, 2);
    prep_w<2><<<( 36 * 2048) / 256, 256, 0, sB>>>(out_w,   36, 2);
    conv_mma<2,1><<<dim3(6, BATCH), 256, CONV_SMEM, sB>>>(
        wp_hi, wp_lo, bin_p, 4, proj_b, nullptr, pos_w, d_out);
    attn_fused<<<BH, 256, 0, sB>>>(concat_k, concat_v, attn_mask, pos_w, pos_b,
                                   d_out + OFF_K, d_out + OFF_V);
    conv_mma<2,2><<<dim3(2, BATCH), 256, CONV_SMEM, sB>>>(
        wo_hi, wo_lo, battn_p, 2, out_b, input, nullptr, d_out);

    // ---- chain A (s0): main weights+conv -> gates ----
    prep_w<0><<<(360 * 2048) / 256, 256, 0, s0>>>(main_w, 360, 4);
    conv_mma<4,0><<<dim3(10, BATCH), 256, CONV_SMEM, s0>>>(
        wm_hi, wm_lo, bin_p, 4, main_b, nullptr, nullptr, d_out);
    gates_kernel<<<16384, 256, 0, s0>>>(c_cur, d_out);

    // ---- join ----
    cudaEventRecord(g_res.evJoin, sB);
    cudaStreamWaitEvent(s0, g_res.evJoin, 0);

    // ---- final fused LayerNorm + LSTM update ----
    ln_final<<<BATCH, 512, 0, s0>>>(norm_w, norm_b, d_out);
}

// round 11
// speedup vs baseline: 1.2582x; 1.2582x over previous
#include <cuda_runtime.h>
#include <cuda_bf16.h>
#include <cuda_fp16.h>
#include <math.h>

// ---------------------------------------------------------------------------
// Problem constants
// ---------------------------------------------------------------------------
#define BATCH 128
#define E_DIM 128
#define NHEAD 8
#define HW 256
#define MEM 8
#define DDIM 4096
#define BH 1024

#define OFF_H  ((size_t)0)
#define OFF_C  ((size_t)4194304)
#define OFF_K  ((size_t)8388608)
#define OFF_V  ((size_t)41943040)

typedef unsigned int u32;

// ---------------------------------------------------------------------------
// Scratch (device globals — allocation-free)
// ---------------------------------------------------------------------------
__device__ float g_cc  [(size_t)BATCH * 640 * HW];
__device__ float g_q   [(size_t)BH * DDIM];
__device__ float g_attn[(size_t)BH * DDIM];
__device__ float g_outp[(size_t)BATCH * E_DIM * HW];

// Pre-swizzled fp16 A tiles: hi = fp16(w), lo = fp16((w-hi)*2048).
// tile = (mtile*9 + tap)*KC + kc ; 64 oc x 64 k, K-major SW128 -> 8192 B.
__device__ __half g_wm_hi[360 * 4096], g_wm_lo[360 * 4096];  // main: 10 mtiles
__device__ __half g_wp_hi[108 * 4096], g_wp_lo[108 * 4096];  // proj: 6
__device__ __half g_wo_hi[ 36 * 4096], g_wo_lo[ 36 * 4096];  // out:  2

__device__ __forceinline__ float sigmoidf_(float x) { return 1.0f / (1.0f + expf(-x)); }

#define SW128(o) ((o) ^ (((o) >> 3) & 0x70))

__device__ __forceinline__ u32 smem_u32(const void* p) {
    u32 a;
    asm("{ .reg .u64 t; cvta.to.shared.u64 t, %1; cvt.u32.u64 %0, t; }" : "=r"(a) : "l"(p));
    return a;
}

__device__ __forceinline__ void ldm_x4(u32* r, u32 addr) {
    asm volatile("ldmatrix.sync.aligned.m8n8.x4.shared.b16 {%0,%1,%2,%3}, [%4];"
        : "=r"(r[0]), "=r"(r[1]), "=r"(r[2]), "=r"(r[3]) : "r"(addr));
}

__device__ __forceinline__ void mma_f16(float* c, const u32* a, u32 b0, u32 b1) {
    asm volatile("mma.sync.aligned.m16n8k16.row.col.f32.f16.f16.f32 "
        "{%0,%1,%2,%3}, {%4,%5,%6,%7}, {%8,%9}, {%0,%1,%2,%3};"
        : "+f"(c[0]), "+f"(c[1]), "+f"(c[2]), "+f"(c[3])
        : "r"(a[0]), "r"(a[1]), "r"(a[2]), "r"(a[3]), "r"(b0), "r"(b1));
}

__device__ __forceinline__ void cp16(u32 dst, const void* src) {
    asm volatile("cp.async.cg.shared.global [%0], [%1], 16;"
                 :: "r"(dst), "l"(src) : "memory");
}
#define CP_COMMIT() asm volatile("cp.async.commit_group;" ::: "memory")
#define CP_WAIT0()  asm volatile("cp.async.wait_group 0;"  ::: "memory")

// B split: bh = fp16(v), bs = fp16(v * 2^-11)   (pairs packed into u32)
__device__ __forceinline__ void splitB(float a, float c, u32& ph, u32& pl) {
    const __half2 hh = __floats2half2_rn(a, c);
    const __half2 ss = __floats2half2_rn(a * 4.8828125e-4f, c * 4.8828125e-4f);
    ph = *(const u32*)&hh; pl = *(const u32*)&ss;
}

// ---------------------------------------------------------------------------
// Stream/event resources (static init — allocation-free in kernel_launch)
// ---------------------------------------------------------------------------
struct OverlapRes {
    cudaStream_t sB;
    cudaEvent_t  evFork, evJoin;
    OverlapRes() {
        cudaStreamCreateWithFlags(&sB, cudaStreamNonBlocking);
        cudaEventCreateWithFlags(&evFork, cudaEventDisableTiming);
        cudaEventCreateWithFlags(&evJoin, cudaEventDisableTiming);
    }
};
static OverlapRes g_res;

// ---------------------------------------------------------------------------
// Weight prep: fp32 [oc][CIN][9] -> swizzled fp16 hi + scaled-residual tiles
// ---------------------------------------------------------------------------
template<int WSEL>
__global__ void __launch_bounds__(256)
prep_w(const float* __restrict__ w, int ntiles, int KC)
{
    const int idx = blockIdx.x * 256 + threadIdx.x;
    if (idx >= ntiles * 2048) return;
    const int tile = idx >> 11, r = idx & 2047, row = r >> 5, kp = r & 31;
    const int kc = tile % KC, t2 = tile / KC, tap = t2 % 9, mtile = t2 / 9;
    const int CIN = KC * 64;
    const int oc  = mtile * 64 + row;
    const int cin = kc * 64 + kp * 2;
    const size_t wb = ((size_t)oc * CIN + cin) * 9 + tap;
    const float f0 = w[wb], f1 = w[wb + 9];
    const __half h0 = __float2half_rn(f0), h1 = __float2half_rn(f1);
    const __half l0 = __float2half_rn((f0 - __half2float(h0)) * 2048.0f);
    const __half l1 = __float2half_rn((f1 - __half2float(h1)) * 2048.0f);
    const __half2 hh = __halves2half2(h0, h1);
    const __half2 ll = __halves2half2(l0, l1);
    const u32 off = SW128((u32)(row * 128 + kp * 4));
    __half* hi = (WSEL == 0) ? g_wm_hi : (WSEL == 1) ? g_wp_hi : g_wo_hi;
    __half* lo = (WSEL == 0) ? g_wm_lo : (WSEL == 1) ? g_wp_lo : g_wo_lo;
    *(u32*)((char*)hi + (size_t)tile * 8192 + off) = *(const u32*)&hh;
    *(u32*)((char*)lo + (size_t)tile * 8192 + off) = *(const u32*)&ll;
}

// ---------------------------------------------------------------------------
// Epilogue store of a float2 (two px) for one output channel
// ---------------------------------------------------------------------------
template<int OUTSEL>
__device__ __forceinline__ void store2(int ocg, int px, float v0, float v1, int b,
                                       const float* __restrict__ resid,
                                       const float* __restrict__ pos_w,
                                       float* __restrict__ d_out)
{
    if (OUTSEL == 0) {
        *(float2*)(g_cc + ((size_t)b * 640 + ocg) * 256 + px) = make_float2(v0, v1);
    } else if (OUTSEL == 2) {
        const float2 r = *(const float2*)(resid + ((size_t)b * 128 + ocg) * 256 + px);
        *(float2*)(g_outp + ((size_t)b * 128 + ocg) * 256 + px) =
            make_float2(v0 + r.x, v1 + r.y);
    } else {
        const int h = ocg / 48, rr = ocg % 48, grp = rr / 16, c = rr % 16;
        const size_t bh = (size_t)b * 8 + h;
        const size_t d0 = (size_t)c * 256 + px;
        if (grp == 0) {
            const float2 pw = *(const float2*)(pos_w + (size_t)7 * 32768 + (size_t)h * 4096 + d0);
            *(float2*)(d_out + OFF_K + (bh * 8 + 7) * 4096 + d0) =
                make_float2(v0 + pw.x, v1 + pw.y);
        } else if (grp == 1) {
            *(float2*)(g_q + bh * 4096 + d0) = make_float2(v0 * 0.015625f, v1 * 0.015625f);
        } else {
            *(float2*)(d_out + OFF_V + (bh * 8 + 7) * 4096 + d0) = make_float2(v0, v1);
        }
    }
}

// ---------------------------------------------------------------------------
// Implicit-GEMM 3x3 conv, mma.sync fp16 2-pass, padded-B shift trick,
// cp.async double-buffered A. 256 threads / 64-oc CTA, 2 CTAs/SM.
// Passes per product: wh*bh + wls*bs   (wls = (w-wh)*2^11, bs = b*2^-11)
// SMEM: A0_hi/lo[0,16K) A1_hi/lo[16K,32K) B_h[32768) B_s[74240) -> 115712
// ---------------------------------------------------------------------------
#define BPAD_ROWS 324
#define BPAD_BYTES (BPAD_ROWS * 128)          // 41472
#define SB_HI 32768
#define SB_LO (32768 + BPAD_BYTES)            // 74240
#define CONV_SMEM (SB_LO + BPAD_BYTES)        // 115712

template<int KC, int INSEL, int OUTSEL>
__global__ void __launch_bounds__(256, 2)
conv_mma(const float* __restrict__ src0, const float* __restrict__ src1,
         const __half* __restrict__ whi, const __half* __restrict__ wlo,
         const float* __restrict__ bias, const float* __restrict__ resid,
         const float* __restrict__ pos_w, float* __restrict__ d_out)
{
    extern __shared__ char smem[];
    const int b     = blockIdx.y;
    const int mtile = blockIdx.x;
    const int tid   = threadIdx.x;
    const int wid   = tid >> 5;
    const int lane  = tid & 31;
    const u32 sbase = smem_u32(smem);

    const int mrow  = (wid & 1) * 32;
    const int nbase = (wid >> 1) * 64;

    const int sel = lane >> 3, r8 = lane & 7;
    const int ar0  = mrow + r8 + ((sel & 1) << 3);
    const int ar1  = ar0 + 16;
    const u32 akad = (u32)((sel >> 1) << 4);
    const u32 ao0b = (u32)(ar0 * 128);
    const u32 ao1b = (u32)(ar1 * 128);
    const u32 asz0 = (u32)((ar0 & 7) << 4);
    const u32 asz1 = (u32)((ar1 & 7) << 4);
    const int pxr  = nbase + r8 + ((sel >> 1) << 3);
    const u32 bkad = (u32)((sel & 1) << 4);
    const int pad00 = ((pxr >> 4) + 1) * 18 + ((pxr & 15) + 1);

    const int yy = tid >> 4, xx = tid & 15;
    const int padw = (yy + 1) * 18 + (xx + 1);

    float acc0[32], acc1[32];
#pragma unroll
    for (int i = 0; i < 32; i++) { acc0[i] = 0.0f; acc1[i] = 0.0f; }

    auto issueA = [&](int tile, int buf) {
        const char* gh = (const char*)whi + (size_t)tile * 8192;
        const char* gl = (const char*)wlo + (size_t)tile * 8192;
        const u32 dh = sbase + (u32)(buf << 14);
        const u32 dl = dh + 8192;
#pragma unroll
        for (int r = 0; r < 2; r++) {
            const u32 o = (u32)(tid * 16 + r * 4096);
            cp16(dh + o, gh + o);
            cp16(dl + o, gl + o);
        }
        CP_COMMIT();
    };

    issueA((mtile * 9) * KC, 0);

    // zero padded-B border rows (persist across kc)
    for (int idx = tid; idx < BPAD_ROWS * 8; idx += 256) {
        const int row = idx >> 3, g = idx & 7;
        const int py = row / 18, px = row % 18;
        if (py == 0 || py == 17 || px == 0 || px == 17) {
            const u32 o = (u32)(row * 128 + g * 16);
            *(uint4*)(smem + SB_HI + o) = make_uint4(0, 0, 0, 0);
            *(uint4*)(smem + SB_LO + o) = make_uint4(0, 0, 0, 0);
        }
    }

    int g = 0;
    for (int kc = 0; kc < KC; kc++) {
        const float* cb;
        if (INSEL == 0) {
            cb = (kc < 2) ? src0 + ((size_t)b * 128 + kc * 64) * 256
                          : src1 + ((size_t)b * 128 + (kc - 2) * 64) * 256;
        } else if (INSEL == 1) {
            cb = src0 + ((size_t)b * 128 + kc * 64) * 256;
        } else {
            cb = g_attn + ((size_t)b * 128 + kc * 64) * 256;
        }

        __syncthreads();   // prev kc compute done -> B writable

        // ---- build padded B interior (once per kc): fp16 bh/bs ----
        {
            const u32 rowb = (u32)(padw * 128);
            const u32 rswz = (u32)((padw & 7) << 4);
#pragma unroll
            for (int gg = 0; gg < 8; gg++) {
                float v[8];
#pragma unroll
                for (int j = 0; j < 8; j++)
                    v[j] = __ldg(cb + (size_t)(gg * 8 + j) * 256 + tid);
                u32 ph[4], pl[4];
#pragma unroll
                for (int j = 0; j < 4; j++) splitB(v[2*j], v[2*j+1], ph[j], pl[j]);
                const u32 o = rowb + ((u32)(gg * 16) ^ rswz);
                *(uint4*)(smem + SB_HI + o) = make_uint4(ph[0], ph[1], ph[2], ph[3]);
                *(uint4*)(smem + SB_LO + o) = make_uint4(pl[0], pl[1], pl[2], pl[3]);
            }
        }

        for (int tap = 0; tap < 9; tap++) {
            const int s = g & 1;
            CP_WAIT0();
            __syncthreads();   // A[s] visible; prev compute done -> buf s^1 free

            {
                int ntap = tap + 1, nkc = kc;
                if (ntap == 9) { ntap = 0; nkc = kc + 1; }
                if (nkc < KC)
                    issueA((mtile * 9 + ntap) * KC + nkc, s ^ 1);
            }

            const int toff = (tap / 3 - 1) * 18 + (tap % 3 - 1);
            const u32 Ab = sbase + (u32)(s << 14);
#pragma unroll
            for (int q = 0; q < 4; q++) {
                const u32 ka = (u32)(q * 32) + akad;
                u32 a0h[4], a0l[4], a1h[4], a1l[4];
                const u32 o0 = ao0b + (ka ^ asz0);
                const u32 o1 = ao1b + (ka ^ asz1);
                ldm_x4(a0h, Ab + o0);
                ldm_x4(a0l, Ab + 8192 + o0);
                ldm_x4(a1h, Ab + o1);
                ldm_x4(a1l, Ab + 8192 + o1);
                const u32 kb = (u32)(q * 32) + bkad;
#pragma unroll
                for (int jj = 0; jj < 4; jj++) {
                    const int pr = pad00 + jj * 18 + toff;
                    const u32 bo = (u32)(pr * 128) + (kb ^ ((u32)(pr & 7) << 4));
                    u32 bh[4], bs[4];
                    ldm_x4(bh, sbase + SB_HI + bo);
                    ldm_x4(bs, sbase + SB_LO + bo);
                    float* c0 = acc0 + jj * 8;
                    mma_f16(c0,     a0h, bh[0], bh[1]);  mma_f16(c0 + 4, a0h, bh[2], bh[3]);
                    mma_f16(c0,     a0l, bs[0], bs[1]);  mma_f16(c0 + 4, a0l, bs[2], bs[3]);
                    float* c1 = acc1 + jj * 8;
                    mma_f16(c1,     a1h, bh[0], bh[1]);  mma_f16(c1 + 4, a1h, bh[2], bh[3]);
                    mma_f16(c1,     a1l, bs[0], bs[1]);  mma_f16(c1 + 4, a1l, bs[2], bs[3]);
                }
            }
            g++;
        }
    }

    const int g2 = lane >> 2, qp = lane & 3;
#pragma unroll
    for (int mt = 0; mt < 2; mt++) {
        const float* am = mt ? acc1 : acc0;
        const int ocg0 = mtile * 64 + mrow + mt * 16 + g2;
        const int ocg1 = ocg0 + 8;
        const float bv0 = __ldg(bias + ocg0);
        const float bv1 = __ldg(bias + ocg1);
#pragma unroll
        for (int t = 0; t < 8; t++) {
            const int px = nbase + t * 8 + qp * 2;
            const float* c = am + t * 4;
            store2<OUTSEL>(ocg0, px, c[0] + bv0, c[1] + bv0, b, resid, pos_w, d_out);
            store2<OUTSEL>(ocg1, px, c[2] + bv1, c[3] + bv1, b, resid, pos_w, d_out);
        }
    }
}

// ---------------------------------------------------------------------------
// LSTM gate fusion
// ---------------------------------------------------------------------------
__global__ void __launch_bounds__(256)
gates_kernel(const float* __restrict__ c_cur, float* __restrict__ d_out)
{
    const size_t idx = (size_t)blockIdx.x * 256 + threadIdx.x;
    if (idx >= (size_t)BATCH * E_DIM * HW) return;
    const int b = (int)(idx >> 15);
    const int r = (int)(idx & 32767);
    const size_t base = (size_t)b * 640 * HW;
    const float ci = g_cc[base + r];
    const float cf = g_cc[base + (size_t)128 * HW + r];
    const float cg = g_cc[base + (size_t)384 * HW + r];
    d_out[OFF_C + idx] = sigmoidf_(cf) * c_cur[idx] + sigmoidf_(ci) * tanhf(cg);
}

// ---------------------------------------------------------------------------
// Fused attention: single deferred reduction for all 8 scores
// ---------------------------------------------------------------------------
__global__ void __launch_bounds__(256)
attn_fused(const float* __restrict__ concat_k, const float* __restrict__ concat_v,
           const unsigned int* __restrict__ mask,
           const float* __restrict__ pos_w, const float* __restrict__ pos_b,
           float* __restrict__ ret_k, float* __restrict__ ret_v)
{
    const int bh  = blockIdx.x;
    const int h   = bh & 7;
    const int tid = threadIdx.x;
    const int wid = tid >> 5, lane = tid & 31;

    float qreg[16];
#pragma unroll
    for (int i = 0; i < 16; i++)
        qreg[i] = g_q[(size_t)bh * DDIM + i * 256 + tid];

    __shared__ float red2[8][MEM];
    __shared__ float w8[MEM];

    float part[MEM];
#pragma unroll
    for (int m = 0; m < MEM; m++) part[m] = 0.0f;

#pragma unroll
    for (int m = 0; m < MEM; m++) {
        const float* ks = (m < 7)
            ? concat_k + ((size_t)bh * MEM + (m + 1)) * DDIM
            : ret_k    + ((size_t)bh * MEM + 7) * DDIM;
        const float* pw = pos_w + (size_t)m * 32768 + (size_t)h * DDIM;
        float p = 0.0f;
#pragma unroll
        for (int i = 0; i < 16; i++) {
            const int idx = i * 256 + tid;
            float kv = ks[idx];
            if (m < 7) {
                kv += pw[idx];
                ret_k[((size_t)bh * MEM + m) * DDIM + idx] = kv;
            }
            p = fmaf(qreg[i], kv, p);
        }
        part[m] = p;
    }

#pragma unroll
    for (int m = 0; m < MEM; m++)
#pragma unroll
        for (int off = 16; off > 0; off >>= 1)
            part[m] += __shfl_down_sync(0xffffffffu, part[m], off);
    if (lane == 0)
#pragma unroll
        for (int m = 0; m < MEM; m++) red2[wid][m] = part[m];
    __syncthreads();

    if (tid == 0) {
        float sc[MEM];
        float mx = -1e30f;
#pragma unroll
        for (int m = 0; m < MEM; m++) {
            float t = 0.0f;
#pragma unroll
            for (int w = 0; w < 8; w++) t += red2[w][m];
            float mf = (m == 7) ? 3.0f : (mask[bh * MEM + m] != 0u ? -1e30f : 0.0f);
            sc[m] = mf + t + pos_b[m * NHEAD + h];
            mx = fmaxf(mx, sc[m]);
        }
        float ssum = 0.0f;
#pragma unroll
        for (int m = 0; m < MEM; m++) { sc[m] = expf(sc[m] - mx); ssum += sc[m]; }
        const float inv = 1.0f / ssum;
#pragma unroll
        for (int m = 0; m < MEM; m++) w8[m] = sc[m] * inv;
    }
    __syncthreads();

    float wl[MEM];
#pragma unroll
    for (int m = 0; m < MEM; m++) wl[m] = w8[m];

#pragma unroll
    for (int i = 0; i < 16; i++) {
        const int idx = i * 256 + tid;
        float acc = 0.0f;
#pragma unroll
        for (int m = 0; m < MEM; m++) {
            float vv;
            if (m < 7) {
                vv = concat_v[((size_t)bh * MEM + (m + 1)) * DDIM + idx];
                ret_v[((size_t)bh * MEM + m) * DDIM + idx] = vv;
            } else {
                vv = ret_v[((size_t)bh * MEM + 7) * DDIM + idx];
            }
            acc = fmaf(wl[m], vv, acc);
        }
        g_attn[(size_t)bh * DDIM + idx] = acc;
    }
}

// ---------------------------------------------------------------------------
// Fused LayerNorm + final LSTM update
// ---------------------------------------------------------------------------
__global__ void __launch_bounds__(512)
ln_final(const float* __restrict__ norm_w, const float* __restrict__ norm_b,
         float* __restrict__ d_out)
{
    const int b   = blockIdx.x;
    const int tid = threadIdx.x;
    const float* p = g_outp + (size_t)b * 32768;

    float s = 0.0f, s2 = 0.0f;
    for (int i = tid; i < 32768; i += 512) {
        const float v = p[i];
        s += v; s2 = fmaf(v, v, s2);
    }
#pragma unroll
    for (int off = 16; off > 0; off >>= 1) {
        s  += __shfl_down_sync(0xffffffffu, s, off);
        s2 += __shfl_down_sync(0xffffffffu, s2, off);
    }
    __shared__ float rs_[16], rs2_[16];
    __shared__ float sh_mu, sh_rs;
    if ((tid & 31) == 0) { rs_[tid >> 5] = s; rs2_[tid >> 5] = s2; }
    __syncthreads();
    if (tid == 0) {
        float ts = 0.0f, ts2 = 0.0f;
#pragma unroll
        for (int w = 0; w < 16; w++) { ts += rs_[w]; ts2 += rs2_[w]; }
        const float mu  = ts * (1.0f / 32768.0f);
        const float var = ts2 * (1.0f / 32768.0f) - mu * mu;
        sh_mu = mu;
        sh_rs = rsqrtf(var + 1e-5f);
    }
    __syncthreads();

    const float mu = sh_mu, rs = sh_rs;
    const size_t cbase = (size_t)b * 640 * HW;
    for (int i = tid; i < 32768; i += 512) {
        const float ln = (p[i] - mu) * rs * norm_w[i] + norm_b[i];
        const float o  = sigmoidf_(g_cc[cbase + (size_t)256 * HW + i]);
        const float a  = sigmoidf_(g_cc[cbase + (size_t)512 * HW + i]);
        const size_t idx = (size_t)b * 32768 + i;
        const float c = d_out[OFF_C + idx] + a * tanhf(ln);
        d_out[OFF_C + idx] = c;
        d_out[OFF_H + idx] = o * tanhf(c);
    }
}

// ---------------------------------------------------------------------------
// Launch — two-stream fork/join (R9 topology)
// ---------------------------------------------------------------------------
extern "C" void kernel_launch(void* const* d_in, const int* in_sizes, int n_in,
                              void* d_out_v, int out_size)
{
    const float* input    = (const float*)d_in[0];
    const float* h_cur    = (const float*)d_in[1];
    const float* c_cur    = (const float*)d_in[2];
    const float* concat_k = (const float*)d_in[3];
    const float* concat_v = (const float*)d_in[4];
    const unsigned int* attn_mask = (const unsigned int*)d_in[5];
    const float* main_w   = (const float*)d_in[6];
    const float* main_b   = (const float*)d_in[7];
    const float* proj_w   = (const float*)d_in[8];
    const float* proj_b   = (const float*)d_in[9];
    const float* out_w    = (const float*)d_in[10];
    const float* out_b    = (const float*)d_in[11];
    const float* norm_w   = (const float*)d_in[12];
    const float* norm_b   = (const float*)d_in[13];
    const float* pos_w    = (const float*)d_in[14];
    const float* pos_b    = (const float*)d_in[15];
    float* d_out = (float*)d_out_v;

    cudaFuncSetAttribute(conv_mma<4,0,0>, cudaFuncAttributeMaxDynamicSharedMemorySize, CONV_SMEM);
    cudaFuncSetAttribute(conv_mma<2,1,1>, cudaFuncAttributeMaxDynamicSharedMemorySize, CONV_SMEM);
    cudaFuncSetAttribute(conv_mma<2,2,2>, cudaFuncAttributeMaxDynamicSharedMemorySize, CONV_SMEM);

    __half *wm_hi, *wm_lo, *wp_hi, *wp_lo, *wo_hi, *wo_lo;
    cudaGetSymbolAddress((void**)&wm_hi, g_wm_hi);
    cudaGetSymbolAddress((void**)&wm_lo, g_wm_lo);
    cudaGetSymbolAddress((void**)&wp_hi, g_wp_hi);
    cudaGetSymbolAddress((void**)&wp_lo, g_wp_lo);
    cudaGetSymbolAddress((void**)&wo_hi, g_wo_hi);
    cudaGetSymbolAddress((void**)&wo_lo, g_wo_lo);

    cudaStream_t s0 = 0;
    cudaStream_t sB = g_res.sB;

    // ---- fork ----
    cudaEventRecord(g_res.evFork, s0);
    cudaStreamWaitEvent(sB, g_res.evFork, 0);

    // ---- chain B (sB): proj weights+conv -> attn -> out conv ----
    prep_w<1><<<(108 * 2048) / 256, 256, 0, sB>>>(proj_w, 108, 2);
    prep_w<2><<<( 36 * 2048) / 256, 256, 0, sB>>>(out_w,   36, 2);
    conv_mma<2,1,1><<<dim3(6, BATCH), 256, CONV_SMEM, sB>>>(
        input, nullptr, wp_hi, wp_lo, proj_b, nullptr, pos_w, d_out);
    attn_fused<<<BH, 256, 0, sB>>>(concat_k, concat_v, attn_mask, pos_w, pos_b,
                                   d_out + OFF_K, d_out + OFF_V);
    conv_mma<2,2,2><<<dim3(2, BATCH), 256, CONV_SMEM, sB>>>(
        nullptr, nullptr, wo_hi, wo_lo, out_b, input, nullptr, d_out);

    // ---- chain A (s0): main weights+conv -> gates ----
    prep_w<0><<<(360 * 2048) / 256, 256, 0, s0>>>(main_w, 360, 4);
    conv_mma<4,0,0><<<dim3(10, BATCH), 256, CONV_SMEM, s0>>>(
        input, h_cur, wm_hi, wm_lo, main_b, nullptr, nullptr, d_out);
    gates_kernel<<<16384, 256, 0, s0>>>(c_cur, d_out);

    // ---- join ----
    cudaEventRecord(g_res.evJoin, sB);
    cudaStreamWaitEvent(s0, g_res.evJoin, 0);

    // ---- final fused LayerNorm + LSTM update ----
    ln_final<<<BATCH, 512, 0, s0>>>(norm_w, norm_b, d_out);
}

// round 12
// speedup vs baseline: 1.8126x; 1.4406x over previous
#include <cuda_runtime.h>
#include <cuda_fp16.h>
#include <math.h>

// ---------------------------------------------------------------------------
// Problem constants
// ---------------------------------------------------------------------------
#define BATCH 128
#define E_DIM 128
#define NHEAD 8
#define HW 256
#define MEM 8
#define DDIM 4096
#define BH 1024

#define OFF_H  ((size_t)0)
#define OFF_C  ((size_t)4194304)
#define OFF_K  ((size_t)8388608)
#define OFF_V  ((size_t)41943040)

typedef unsigned int u32;

// ---------------------------------------------------------------------------
// Scratch (device globals — allocation-free)
// ---------------------------------------------------------------------------
__device__ float g_cc  [(size_t)BATCH * 640 * HW];
__device__ float g_q   [(size_t)BH * DDIM];
__device__ float g_attn[(size_t)BH * DDIM];
__device__ float g_outp[(size_t)BATCH * E_DIM * HW];

// Pre-swizzled fp16 A tiles. tile = (mtile*9 + tap)*KC + kc ;
// 64 oc x 64 k, K-major SW128 -> 8192 B.
__device__ __half g_wm[360 * 4096];  // main: 10 mtiles
__device__ __half g_wp[108 * 4096];  // proj: 6
__device__ __half g_wo[ 36 * 4096];  // out:  2

__device__ __forceinline__ float sigmoidf_(float x) { return 1.0f / (1.0f + expf(-x)); }

#define SW128(o) ((o) ^ (((o) >> 3) & 0x70))

__device__ __forceinline__ u32 smem_u32(const void* p) {
    u32 a;
    asm("{ .reg .u64 t; cvta.to.shared.u64 t, %1; cvt.u32.u64 %0, t; }" : "=r"(a) : "l"(p));
    return a;
}

__device__ __forceinline__ void ldm_x4(u32* r, u32 addr) {
    asm volatile("ldmatrix.sync.aligned.m8n8.x4.shared.b16 {%0,%1,%2,%3}, [%4];"
        : "=r"(r[0]), "=r"(r[1]), "=r"(r[2]), "=r"(r[3]) : "r"(addr));
}

__device__ __forceinline__ void mma_f16(float* c, const u32* a, u32 b0, u32 b1) {
    asm volatile("mma.sync.aligned.m16n8k16.row.col.f32.f16.f16.f32 "
        "{%0,%1,%2,%3}, {%4,%5,%6,%7}, {%8,%9}, {%0,%1,%2,%3};"
        : "+f"(c[0]), "+f"(c[1]), "+f"(c[2]), "+f"(c[3])
        : "r"(a[0]), "r"(a[1]), "r"(a[2]), "r"(a[3]), "r"(b0), "r"(b1));
}

__device__ __forceinline__ void cp16(u32 dst, const void* src) {
    asm volatile("cp.async.cg.shared.global [%0], [%1], 16;"
                 :: "r"(dst), "l"(src) : "memory");
}
#define CP_COMMIT() asm volatile("cp.async.commit_group;" ::: "memory")
#define CP_WAIT0()  asm volatile("cp.async.wait_group 0;"  ::: "memory")

// ---------------------------------------------------------------------------
// Stream/event resources (static init — allocation-free in kernel_launch)
// ---------------------------------------------------------------------------
struct OverlapRes {
    cudaStream_t sB;
    cudaEvent_t  evFork, evJoin;
    OverlapRes() {
        cudaStreamCreateWithFlags(&sB, cudaStreamNonBlocking);
        cudaEventCreateWithFlags(&evFork, cudaEventDisableTiming);
        cudaEventCreateWithFlags(&evJoin, cudaEventDisableTiming);
    }
};
static OverlapRes g_res;

// ---------------------------------------------------------------------------
// Weight prep: fp32 [oc][CIN][9] -> swizzled fp16 64x64 K-major tiles
// ---------------------------------------------------------------------------
template<int WSEL>
__global__ void __launch_bounds__(256)
prep_w(const float* __restrict__ w, int ntiles, int KC)
{
    const int idx = blockIdx.x * 256 + threadIdx.x;
    if (idx >= ntiles * 2048) return;
    const int tile = idx >> 11, r = idx & 2047, row = r >> 5, kp = r & 31;
    const int kc = tile % KC, t2 = tile / KC, tap = t2 % 9, mtile = t2 / 9;
    const int CIN = KC * 64;
    const int oc  = mtile * 64 + row;
    const int cin = kc * 64 + kp * 2;
    const size_t wb = ((size_t)oc * CIN + cin) * 9 + tap;
    const __half2 hh = __floats2half2_rn(w[wb], w[wb + 9]);
    const u32 off = SW128((u32)(row * 128 + kp * 4));
    __half* hi = (WSEL == 0) ? g_wm : (WSEL == 1) ? g_wp : g_wo;
    *(u32*)((char*)hi + (size_t)tile * 8192 + off) = *(const u32*)&hh;
}

// ---------------------------------------------------------------------------
// Epilogue store of a float2 (two px) for one output channel
// ---------------------------------------------------------------------------
template<int OUTSEL>
__device__ __forceinline__ void store2(int ocg, int px, float v0, float v1, int b,
                                       const float* __restrict__ resid,
                                       const float* __restrict__ pos_w,
                                       float* __restrict__ d_out)
{
    if (OUTSEL == 0) {
        *(float2*)(g_cc + ((size_t)b * 640 + ocg) * 256 + px) = make_float2(v0, v1);
    } else if (OUTSEL == 2) {
        const float2 r = *(const float2*)(resid + ((size_t)b * 128 + ocg) * 256 + px);
        *(float2*)(g_outp + ((size_t)b * 128 + ocg) * 256 + px) =
            make_float2(v0 + r.x, v1 + r.y);
    } else {
        const int h = ocg / 48, rr = ocg % 48, grp = rr / 16, c = rr % 16;
        const size_t bh = (size_t)b * 8 + h;
        const size_t d0 = (size_t)c * 256 + px;
        if (grp == 0) {
            const float2 pw = *(const float2*)(pos_w + (size_t)7 * 32768 + (size_t)h * 4096 + d0);
            *(float2*)(d_out + OFF_K + (bh * 8 + 7) * 4096 + d0) =
                make_float2(v0 + pw.x, v1 + pw.y);
        } else if (grp == 1) {
            *(float2*)(g_q + bh * 4096 + d0) = make_float2(v0 * 0.015625f, v1 * 0.015625f);
        } else {
            *(float2*)(d_out + OFF_V + (bh * 8 + 7) * 4096 + d0) = make_float2(v0, v1);
        }
    }
}

// ---------------------------------------------------------------------------
// Implicit-GEMM 3x3 conv, mma.sync fp16 single-pass, padded-B shift trick,
// cp.async double-buffered A. 256 threads / 64-oc CTA, 2 CTAs/SM.
// SMEM: A0[0,8K) A1[8K,16K) B[16384, +41472) -> 57856
// ---------------------------------------------------------------------------
#define BPAD_ROWS 324
#define BPAD_BYTES (BPAD_ROWS * 128)          // 41472
#define SB 16384
#define CONV_SMEM (SB + BPAD_BYTES)           // 57856

template<int KC, int INSEL, int OUTSEL>
__global__ void __launch_bounds__(256, 2)
conv_mma(const float* __restrict__ src0, const float* __restrict__ src1,
         const __half* __restrict__ whi,
         const float* __restrict__ bias, const float* __restrict__ resid,
         const float* __restrict__ pos_w, float* __restrict__ d_out)
{
    extern __shared__ char smem[];
    const int b     = blockIdx.y;
    const int mtile = blockIdx.x;
    const int tid   = threadIdx.x;
    const int wid   = tid >> 5;
    const int lane  = tid & 31;
    const u32 sbase = smem_u32(smem);

    const int mrow  = (wid & 1) * 32;
    const int nbase = (wid >> 1) * 64;

    const int sel = lane >> 3, r8 = lane & 7;
    const int ar0  = mrow + r8 + ((sel & 1) << 3);
    const int ar1  = ar0 + 16;
    const u32 akad = (u32)((sel >> 1) << 4);
    const u32 ao0b = (u32)(ar0 * 128);
    const u32 ao1b = (u32)(ar1 * 128);
    const u32 asz0 = (u32)((ar0 & 7) << 4);
    const u32 asz1 = (u32)((ar1 & 7) << 4);
    const int pxr  = nbase + r8 + ((sel >> 1) << 3);
    const u32 bkad = (u32)((sel & 1) << 4);
    const int pad00 = ((pxr >> 4) + 1) * 18 + ((pxr & 15) + 1);

    const int yy = tid >> 4, xx = tid & 15;
    const int padw = (yy + 1) * 18 + (xx + 1);

    float acc0[32], acc1[32];
#pragma unroll
    for (int i = 0; i < 32; i++) { acc0[i] = 0.0f; acc1[i] = 0.0f; }

    auto issueA = [&](int tile, int buf) {
        const char* gh = (const char*)whi + (size_t)tile * 8192;
        const u32 dh = sbase + (u32)(buf << 13);
        const u32 o = (u32)(tid * 16);
        cp16(dh + o, gh + o);
        cp16(dh + o + 4096, gh + o + 4096);
        CP_COMMIT();
    };

    issueA((mtile * 9) * KC, 0);

    // zero padded-B border rows (persist across kc)
    for (int idx = tid; idx < BPAD_ROWS * 8; idx += 256) {
        const int row = idx >> 3, g = idx & 7;
        const int py = row / 18, px = row % 18;
        if (py == 0 || py == 17 || px == 0 || px == 17) {
            *(uint4*)(smem + SB + (u32)(row * 128 + g * 16)) = make_uint4(0, 0, 0, 0);
        }
    }

    int g = 0;
    for (int kc = 0; kc < KC; kc++) {
        const float* cb;
        if (INSEL == 0) {
            cb = (kc < 2) ? src0 + ((size_t)b * 128 + kc * 64) * 256
                          : src1 + ((size_t)b * 128 + (kc - 2) * 64) * 256;
        } else if (INSEL == 1) {
            cb = src0 + ((size_t)b * 128 + kc * 64) * 256;
        } else {
            cb = g_attn + ((size_t)b * 128 + kc * 64) * 256;
        }

        __syncthreads();   // prev kc compute done -> B writable

        // ---- build padded B interior (once per kc): fp16 ----
        {
            const u32 rowb = (u32)(padw * 128);
            const u32 rswz = (u32)((padw & 7) << 4);
#pragma unroll
            for (int gg = 0; gg < 8; gg++) {
                float v[8];
#pragma unroll
                for (int j = 0; j < 8; j++)
                    v[j] = __ldg(cb + (size_t)(gg * 8 + j) * 256 + tid);
                u32 ph[4];
#pragma unroll
                for (int j = 0; j < 4; j++) {
                    const __half2 hh = __floats2half2_rn(v[2*j], v[2*j+1]);
                    ph[j] = *(const u32*)&hh;
                }
                const u32 o = rowb + ((u32)(gg * 16) ^ rswz);
                *(uint4*)(smem + SB + o) = make_uint4(ph[0], ph[1], ph[2], ph[3]);
            }
        }

        for (int tap = 0; tap < 9; tap++) {
            const int s = g & 1;
            CP_WAIT0();
            __syncthreads();   // A[s] visible; prev compute done -> buf s^1 free

            {
                int ntap = tap + 1, nkc = kc;
                if (ntap == 9) { ntap = 0; nkc = kc + 1; }
                if (nkc < KC)
                    issueA((mtile * 9 + ntap) * KC + nkc, s ^ 1);
            }

            const int toff = (tap / 3 - 1) * 18 + (tap % 3 - 1);
            const u32 Ab = sbase + (u32)(s << 13);
#pragma unroll
            for (int q = 0; q < 4; q++) {
                const u32 ka = (u32)(q * 32) + akad;
                u32 a0[4], a1[4];
                ldm_x4(a0, Ab + ao0b + (ka ^ asz0));
                ldm_x4(a1, Ab + ao1b + (ka ^ asz1));
                const u32 kb = (u32)(q * 32) + bkad;
#pragma unroll
                for (int jj = 0; jj < 4; jj++) {
                    const int pr = pad00 + jj * 18 + toff;
                    const u32 bo = (u32)(pr * 128) + (kb ^ ((u32)(pr & 7) << 4));
                    u32 bh[4];
                    ldm_x4(bh, sbase + SB + bo);
                    float* c0 = acc0 + jj * 8;
                    mma_f16(c0,     a0, bh[0], bh[1]);  mma_f16(c0 + 4, a0, bh[2], bh[3]);
                    float* c1 = acc1 + jj * 8;
                    mma_f16(c1,     a1, bh[0], bh[1]);  mma_f16(c1 + 4, a1, bh[2], bh[3]);
                }
            }
            g++;
        }
    }

    const int g2 = lane >> 2, qp = lane & 3;
#pragma unroll
    for (int mt = 0; mt < 2; mt++) {
        const float* am = mt ? acc1 : acc0;
        const int ocg0 = mtile * 64 + mrow + mt * 16 + g2;
        const int ocg1 = ocg0 + 8;
        const float bv0 = __ldg(bias + ocg0);
        const float bv1 = __ldg(bias + ocg1);
#pragma unroll
        for (int t = 0; t < 8; t++) {
            const int px = nbase + t * 8 + qp * 2;
            const float* c = am + t * 4;
            store2<OUTSEL>(ocg0, px, c[0] + bv0, c[1] + bv0, b, resid, pos_w, d_out);
            store2<OUTSEL>(ocg1, px, c[2] + bv1, c[3] + bv1, b, resid, pos_w, d_out);
        }
    }
}

// ---------------------------------------------------------------------------
// LSTM gate fusion
// ---------------------------------------------------------------------------
__global__ void __launch_bounds__(256)
gates_kernel(const float* __restrict__ c_cur, float* __restrict__ d_out)
{
    const size_t idx = (size_t)blockIdx.x * 256 + threadIdx.x;
    if (idx >= (size_t)BATCH * E_DIM * HW) return;
    const int b = (int)(idx >> 15);
    const int r = (int)(idx & 32767);
    const size_t base = (size_t)b * 640 * HW;
    const float ci = g_cc[base + r];
    const float cf = g_cc[base + (size_t)128 * HW + r];
    const float cg = g_cc[base + (size_t)384 * HW + r];
    d_out[OFF_C + idx] = sigmoidf_(cf) * c_cur[idx] + sigmoidf_(ci) * tanhf(cg);
}

// ---------------------------------------------------------------------------
// Fused attention: single deferred reduction for all 8 scores
// ---------------------------------------------------------------------------
__global__ void __launch_bounds__(256)
attn_fused(const float* __restrict__ concat_k, const float* __restrict__ concat_v,
           const unsigned int* __restrict__ mask,
           const float* __restrict__ pos_w, const float* __restrict__ pos_b,
           float* __restrict__ ret_k, float* __restrict__ ret_v)
{
    const int bh  = blockIdx.x;
    const int h   = bh & 7;
    const int tid = threadIdx.x;
    const int wid = tid >> 5, lane = tid & 31;

    float qreg[16];
#pragma unroll
    for (int i = 0; i < 16; i++)
        qreg[i] = g_q[(size_t)bh * DDIM + i * 256 + tid];

    __shared__ float red2[8][MEM];
    __shared__ float w8[MEM];

    float part[MEM];
#pragma unroll
    for (int m = 0; m < MEM; m++) part[m] = 0.0f;

#pragma unroll
    for (int m = 0; m < MEM; m++) {
        const float* ks = (m < 7)
            ? concat_k + ((size_t)bh * MEM + (m + 1)) * DDIM
            : ret_k    + ((size_t)bh * MEM + 7) * DDIM;
        const float* pw = pos_w + (size_t)m * 32768 + (size_t)h * DDIM;
        float p = 0.0f;
#pragma unroll
        for (int i = 0; i < 16; i++) {
            const int idx = i * 256 + tid;
            float kv = ks[idx];
            if (m < 7) {
                kv += pw[idx];
                ret_k[((size_t)bh * MEM + m) * DDIM + idx] = kv;
            }
            p = fmaf(qreg[i], kv, p);
        }
        part[m] = p;
    }

#pragma unroll
    for (int m = 0; m < MEM; m++)
#pragma unroll
        for (int off = 16; off > 0; off >>= 1)
            part[m] += __shfl_down_sync(0xffffffffu, part[m], off);
    if (lane == 0)
#pragma unroll
        for (int m = 0; m < MEM; m++) red2[wid][m] = part[m];
    __syncthreads();

    if (tid == 0) {
        float sc[MEM];
        float mx = -1e30f;
#pragma unroll
        for (int m = 0; m < MEM; m++) {
            float t = 0.0f;
#pragma unroll
            for (int w = 0; w < 8; w++) t += red2[w][m];
            float mf = (m == 7) ? 3.0f : (mask[bh * MEM + m] != 0u ? -1e30f : 0.0f);
            sc[m] = mf + t + pos_b[m * NHEAD + h];
            mx = fmaxf(mx, sc[m]);
        }
        float ssum = 0.0f;
#pragma unroll
        for (int m = 0; m < MEM; m++) { sc[m] = expf(sc[m] - mx); ssum += sc[m]; }
        const float inv = 1.0f / ssum;
#pragma unroll
        for (int m = 0; m < MEM; m++) w8[m] = sc[m] * inv;
    }
    __syncthreads();

    float wl[MEM];
#pragma unroll
    for (int m = 0; m < MEM; m++) wl[m] = w8[m];

#pragma unroll
    for (int i = 0; i < 16; i++) {
        const int idx = i * 256 + tid;
        float acc = 0.0f;
#pragma unroll
        for (int m = 0; m < MEM; m++) {
            float vv;
            if (m < 7) {
                vv = concat_v[((size_t)bh * MEM + (m + 1)) * DDIM + idx];
                ret_v[((size_t)bh * MEM + m) * DDIM + idx] = vv;
            } else {
                vv = ret_v[((size_t)bh * MEM + 7) * DDIM + idx];
            }
            acc = fmaf(wl[m], vv, acc);
        }
        g_attn[(size_t)bh * DDIM + idx] = acc;
    }
}

// ---------------------------------------------------------------------------
// Fused LayerNorm + final LSTM update
// ---------------------------------------------------------------------------
__global__ void __launch_bounds__(512)
ln_final(const float* __restrict__ norm_w, const float* __restrict__ norm_b,
         float* __restrict__ d_out)
{
    const int b   = blockIdx.x;
    const int tid = threadIdx.x;
    const float* p = g_outp + (size_t)b * 32768;

    float s = 0.0f, s2 = 0.0f;
    for (int i = tid; i < 32768; i += 512) {
        const float v = p[i];
        s += v; s2 = fmaf(v, v, s2);
    }
#pragma unroll
    for (int off = 16; off > 0; off >>= 1) {
        s  += __shfl_down_sync(0xffffffffu, s, off);
        s2 += __shfl_down_sync(0xffffffffu, s2, off);
    }
    __shared__ float rs_[16], rs2_[16];
    __shared__ float sh_mu, sh_rs;
    if ((tid & 31) == 0) { rs_[tid >> 5] = s; rs2_[tid >> 5] = s2; }
    __syncthreads();
    if (tid == 0) {
        float ts = 0.0f, ts2 = 0.0f;
#pragma unroll
        for (int w = 0; w < 16; w++) { ts += rs_[w]; ts2 += rs2_[w]; }
        const float mu  = ts * (1.0f / 32768.0f);
        const float var = ts2 * (1.0f / 32768.0f) - mu * mu;
        sh_mu = mu;
        sh_rs = rsqrtf(var + 1e-5f);
    }
    __syncthreads();

    const float mu = sh_mu, rs = sh_rs;
    const size_t cbase = (size_t)b * 640 * HW;
    for (int i = tid; i < 32768; i += 512) {
        const float ln = (p[i] - mu) * rs * norm_w[i] + norm_b[i];
        const float o  = sigmoidf_(g_cc[cbase + (size_t)256 * HW + i]);
        const float a  = sigmoidf_(g_cc[cbase + (size_t)512 * HW + i]);
        const size_t idx = (size_t)b * 32768 + i;
        const float c = d_out[OFF_C + idx] + a * tanhf(ln);
        d_out[OFF_C + idx] = c;
        d_out[OFF_H + idx] = o * tanhf(c);
    }
}

// ---------------------------------------------------------------------------
// Launch — two-stream fork/join (R9/R11 topology)
// ---------------------------------------------------------------------------
extern "C" void kernel_launch(void* const* d_in, const int* in_sizes, int n_in,
                              void* d_out_v, int out_size)
{
    const float* input    = (const float*)d_in[0];
    const float* h_cur    = (const float*)d_in[1];
    const float* c_cur    = (const float*)d_in[2];
    const float* concat_k = (const float*)d_in[3];
    const float* concat_v = (const float*)d_in[4];
    const unsigned int* attn_mask = (const unsigned int*)d_in[5];
    const float* main_w   = (const float*)d_in[6];
    const float* main_b   = (const float*)d_in[7];
    const float* proj_w   = (const float*)d_in[8];
    const float* proj_b   = (const float*)d_in[9];
    const float* out_w    = (const float*)d_in[10];
    const float* out_b    = (const float*)d_in[11];
    const float* norm_w   = (const float*)d_in[12];
    const float* norm_b   = (const float*)d_in[13];
    const float* pos_w    = (const float*)d_in[14];
    const float* pos_b    = (const float*)d_in[15];
    float* d_out = (float*)d_out_v;

    cudaFuncSetAttribute(conv_mma<4,0,0>, cudaFuncAttributeMaxDynamicSharedMemorySize, CONV_SMEM);
    cudaFuncSetAttribute(conv_mma<2,1,1>, cudaFuncAttributeMaxDynamicSharedMemorySize, CONV_SMEM);
    cudaFuncSetAttribute(conv_mma<2,2,2>, cudaFuncAttributeMaxDynamicSharedMemorySize, CONV_SMEM);

    __half *wm, *wp, *wo;
    cudaGetSymbolAddress((void**)&wm, g_wm);
    cudaGetSymbolAddress((void**)&wp, g_wp);
    cudaGetSymbolAddress((void**)&wo, g_wo);

    cudaStream_t s0 = 0;
    cudaStream_t sB = g_res.sB;

    // ---- fork ----
    cudaEventRecord(g_res.evFork, s0);
    cudaStreamWaitEvent(sB, g_res.evFork, 0);

    // ---- chain B (sB): proj weights+conv -> attn -> out conv ----
    prep_w<1><<<(108 * 2048) / 256, 256, 0, sB>>>(proj_w, 108, 2);
    prep_w<2><<<( 36 * 2048) / 256, 256, 0, sB>>>(out_w,   36, 2);
    conv_mma<2,1,1><<<dim3(6, BATCH), 256, CONV_SMEM, sB>>>(
        input, nullptr, wp, proj_b, nullptr, pos_w, d_out);
    attn_fused<<<BH, 256, 0, sB>>>(concat_k, concat_v, attn_mask, pos_w, pos_b,
                                   d_out + OFF_K, d_out + OFF_V);
    conv_mma<2,2,2><<<dim3(2, BATCH), 256, CONV_SMEM, sB>>>(
        nullptr, nullptr, wo, out_b, input, nullptr, d_out);

    // ---- chain A (s0): main weights+conv -> gates ----
    prep_w<0><<<(360 * 2048) / 256, 256, 0, s0>>>(main_w, 360, 4);
    conv_mma<4,0,0><<<dim3(10, BATCH), 256, CONV_SMEM, s0>>>(
        input, h_cur, wm, main_b, nullptr, nullptr, d_out);
    gates_kernel<<<16384, 256, 0, s0>>>(c_cur, d_out);

    // ---- join ----
    cudaEventRecord(g_res.evJoin, sB);
    cudaStreamWaitEvent(s0, g_res.evJoin, 0);

    // ---- final fused LayerNorm + LSTM update ----
    ln_final<<<BATCH, 512, 0, s0>>>(norm_w, norm_b, d_out);
}

// round 13
// speedup vs baseline: 2.2746x; 1.2548x over previous
#include <cuda_runtime.h>
#include <cuda_fp16.h>
#include <math.h>

// ---------------------------------------------------------------------------
// Problem constants
// ---------------------------------------------------------------------------
#define BATCH 128
#define E_DIM 128
#define NHEAD 8
#define HW 256
#define MEM 8
#define DDIM 4096
#define BH 1024

#define OFF_H  ((size_t)0)
#define OFF_C  ((size_t)4194304)
#define OFF_K  ((size_t)8388608)
#define OFF_V  ((size_t)41943040)

typedef unsigned int u32;

// padded fp16 image: 18x18 rows x 64 ch = 324 rows x 128 B = 41472 B per kc
#define BPAD_ROWS 324
#define BPAD_BYTES (BPAD_ROWS * 128)

// ---------------------------------------------------------------------------
// Scratch (device globals — allocation-free; zero-init keeps never-written
// padded-image border rows zero forever)
// ---------------------------------------------------------------------------
__device__ float g_cc  [(size_t)BATCH * 640 * HW];
__device__ float g_q   [(size_t)BH * DDIM];
__device__ float g_outp[(size_t)BATCH * E_DIM * HW];

// padded fp16 input images: [b][kc(4)][20736 halves]  (input kc0-1, h_cur kc2-3)
__device__ __align__(16) __half g_bin  [(size_t)BATCH * 4 * 20736];
// padded fp16 attention-output images: [b][kc(2)][20736 halves]
__device__ __align__(16) __half g_battn[(size_t)BATCH * 2 * 20736];

// Pre-swizzled fp16 A tiles. tile = (mtile*9 + tap)*KC + kc ; 64x64 -> 8192 B.
__device__ __align__(16) __half g_wm[360 * 4096];
__device__ __align__(16) __half g_wp[108 * 4096];
__device__ __align__(16) __half g_wo[ 36 * 4096];

__device__ __forceinline__ float sigmoidf_(float x) { return 1.0f / (1.0f + expf(-x)); }

#define SW128(o) ((o) ^ (((o) >> 3) & 0x70))

__device__ __forceinline__ u32 smem_u32(const void* p) {
    u32 a;
    asm("{ .reg .u64 t; cvta.to.shared.u64 t, %1; cvt.u32.u64 %0, t; }" : "=r"(a) : "l"(p));
    return a;
}

__device__ __forceinline__ void ldm_x4(u32* r, u32 addr) {
    asm volatile("ldmatrix.sync.aligned.m8n8.x4.shared.b16 {%0,%1,%2,%3}, [%4];"
        : "=r"(r[0]), "=r"(r[1]), "=r"(r[2]), "=r"(r[3]) : "r"(addr));
}

__device__ __forceinline__ void mma_f16(float* c, const u32* a, u32 b0, u32 b1) {
    asm volatile("mma.sync.aligned.m16n8k16.row.col.f32.f16.f16.f32 "
        "{%0,%1,%2,%3}, {%4,%5,%6,%7}, {%8,%9}, {%0,%1,%2,%3};"
        : "+f"(c[0]), "+f"(c[1]), "+f"(c[2]), "+f"(c[3])
        : "r"(a[0]), "r"(a[1]), "r"(a[2]), "r"(a[3]), "r"(b0), "r"(b1));
}

__device__ __forceinline__ void cp16(u32 dst, const void* src) {
    asm volatile("cp.async.cg.shared.global [%0], [%1], 16;"
                 :: "r"(dst), "l"(src) : "memory");
}
#define CP_COMMIT() asm volatile("cp.async.commit_group;" ::: "memory")
#define CP_WAIT0()  asm volatile("cp.async.wait_group 0;"  ::: "memory")

// ---------------------------------------------------------------------------
// Stream/event resources (static init — allocation-free in kernel_launch)
// ---------------------------------------------------------------------------
struct OverlapRes {
    cudaStream_t sB;
    cudaEvent_t  evFork, evJoin;
    OverlapRes() {
        cudaStreamCreateWithFlags(&sB, cudaStreamNonBlocking);
        cudaEventCreateWithFlags(&evFork, cudaEventDisableTiming);
        cudaEventCreateWithFlags(&evJoin, cudaEventDisableTiming);
    }
};
static OverlapRes g_res;

// ---------------------------------------------------------------------------
// Input prep: fp32 (input | h_cur) -> padded fp16 images in gmem.
// block = (kc, b); thread = interior pixel (borders stay zero-init).
// ---------------------------------------------------------------------------
__global__ void __launch_bounds__(256)
prep_in(const float* __restrict__ input, const float* __restrict__ h_cur)
{
    const int kc = blockIdx.x, b = blockIdx.y;
    const int tid = threadIdx.x;
    const float* cb = (kc < 2) ? input + ((size_t)b * 128 + kc * 64) * 256
                               : h_cur + ((size_t)b * 128 + (kc - 2) * 64) * 256;
    char* dst = (char*)g_bin + (size_t)(b * 4 + kc) * BPAD_BYTES;

    const int padw = ((tid >> 4) + 1) * 18 + (tid & 15) + 1;
    const u32 rowb = (u32)(padw * 128);
    const u32 rswz = (u32)((padw & 7) << 4);
#pragma unroll
    for (int gg = 0; gg < 8; gg++) {
        float v[8];
#pragma unroll
        for (int j = 0; j < 8; j++)
            v[j] = __ldg(cb + (size_t)(gg * 8 + j) * 256 + tid);
        u32 ph[4];
#pragma unroll
        for (int j = 0; j < 4; j++) {
            const __half2 hh = __floats2half2_rn(v[2*j], v[2*j+1]);
            ph[j] = *(const u32*)&hh;
        }
        *(uint4*)(dst + rowb + ((u32)(gg * 16) ^ rswz)) = make_uint4(ph[0], ph[1], ph[2], ph[3]);
    }
}

// ---------------------------------------------------------------------------
// Weight prep: fp32 [oc][CIN][9] -> swizzled fp16 64x64 K-major tiles
// ---------------------------------------------------------------------------
template<int WSEL>
__global__ void __launch_bounds__(256)
prep_w(const float* __restrict__ w, int ntiles, int KC)
{
    const int idx = blockIdx.x * 256 + threadIdx.x;
    if (idx >= ntiles * 2048) return;
    const int tile = idx >> 11, r = idx & 2047, row = r >> 5, kp = r & 31;
    const int kc = tile % KC, t2 = tile / KC, tap = t2 % 9, mtile = t2 / 9;
    const int CIN = KC * 64;
    const int oc  = mtile * 64 + row;
    const int cin = kc * 64 + kp * 2;
    const size_t wb = ((size_t)oc * CIN + cin) * 9 + tap;
    const __half2 hh = __floats2half2_rn(w[wb], w[wb + 9]);
    const u32 off = SW128((u32)(row * 128 + kp * 4));
    __half* hi = (WSEL == 0) ? g_wm : (WSEL == 1) ? g_wp : g_wo;
    *(u32*)((char*)hi + (size_t)tile * 8192 + off) = *(const u32*)&hh;
}

// ---------------------------------------------------------------------------
// Epilogue store of a float2 (two px) for one output channel
// ---------------------------------------------------------------------------
template<int OUTSEL>
__device__ __forceinline__ void store2(int ocg, int px, float v0, float v1, int b,
                                       const float* __restrict__ resid,
                                       const float* __restrict__ pos_w,
                                       float* __restrict__ d_out)
{
    if (OUTSEL == 0) {
        *(float2*)(g_cc + ((size_t)b * 640 + ocg) * 256 + px) = make_float2(v0, v1);
    } else if (OUTSEL == 2) {
        const float2 r = *(const float2*)(resid + ((size_t)b * 128 + ocg) * 256 + px);
        *(float2*)(g_outp + ((size_t)b * 128 + ocg) * 256 + px) =
            make_float2(v0 + r.x, v1 + r.y);
    } else {
        const int h = ocg / 48, rr = ocg % 48, grp = rr / 16, c = rr % 16;
        const size_t bh = (size_t)b * 8 + h;
        const size_t d0 = (size_t)c * 256 + px;
        if (grp == 0) {
            const float2 pw = *(const float2*)(pos_w + (size_t)7 * 32768 + (size_t)h * 4096 + d0);
            *(float2*)(d_out + OFF_K + (bh * 8 + 7) * 4096 + d0) =
                make_float2(v0 + pw.x, v1 + pw.y);
        } else if (grp == 1) {
            *(float2*)(g_q + bh * 4096 + d0) = make_float2(v0 * 0.015625f, v1 * 0.015625f);
        } else {
            *(float2*)(d_out + OFF_V + (bh * 8 + 7) * 4096 + d0) = make_float2(v0, v1);
        }
    }
}

// ---------------------------------------------------------------------------
// Implicit-GEMM 3x3 conv, fp16 single-pass mma.sync, padded-B shift trick.
// A double-buffered (per tap) AND B double-buffered (per kc), both cp.async —
// no in-kernel conversion at all. 256 threads / 64-oc CTA, 2 CTAs/SM.
// SMEM: A0[0,8K) A1[8K,16K) B0[16384,+41472) B1[57856,+41472) -> 99328
// ---------------------------------------------------------------------------
#define SB0 16384
#define SB1 57856
#define CONV_SMEM 99328

template<int KC, int OUTSEL>
__global__ void __launch_bounds__(256, 2)
conv_mma(const __half* __restrict__ whi,
         const char* __restrict__ ball, int bstride,
         const float* __restrict__ bias, const float* __restrict__ resid,
         const float* __restrict__ pos_w, float* __restrict__ d_out)
{
    extern __shared__ char smem[];
    const int b     = blockIdx.y;
    const int mtile = blockIdx.x;
    const int tid   = threadIdx.x;
    const int wid   = tid >> 5;
    const int lane  = tid & 31;
    const u32 sbase = smem_u32(smem);

    const int mrow  = (wid & 1) * 32;
    const int nbase = (wid >> 1) * 64;

    const int sel = lane >> 3, r8 = lane & 7;
    const int ar0  = mrow + r8 + ((sel & 1) << 3);
    const int ar1  = ar0 + 16;
    const u32 akad = (u32)((sel >> 1) << 4);
    const u32 ao0b = (u32)(ar0 * 128);
    const u32 ao1b = (u32)(ar1 * 128);
    const u32 asz0 = (u32)((ar0 & 7) << 4);
    const u32 asz1 = (u32)((ar1 & 7) << 4);
    const int pxr  = nbase + r8 + ((sel >> 1) << 3);
    const u32 bkad = (u32)((sel & 1) << 4);
    const int pad00 = ((pxr >> 4) + 1) * 18 + ((pxr & 15) + 1);

    float acc0[32], acc1[32];
#pragma unroll
    for (int i = 0; i < 32; i++) { acc0[i] = 0.0f; acc1[i] = 0.0f; }

    auto bimg = [&](int kc) {
        return ball + ((size_t)b * bstride + kc) * BPAD_BYTES;
    };
    auto issueA = [&](int tile, int buf) {
        const char* gh = (const char*)whi + (size_t)tile * 8192;
        const u32 dh = sbase + (u32)(buf << 13);
        const u32 o = (u32)(tid * 16);
        cp16(dh + o, gh + o);
        cp16(dh + o + 4096, gh + o + 4096);
    };

    // prologue: full B(kc0) into buf0 + A(kc0,tap0) into buf0, one group
    {
        const char* src = bimg(0);
        for (u32 o = (u32)tid * 16; o < BPAD_BYTES; o += 4096)
            cp16(sbase + SB0 + o, src + o);
        issueA((mtile * 9) * KC, 0);
        CP_COMMIT();
    }

    int g = 0, bbuf = 0;
    for (int kc = 0; kc < KC; kc++) {
        const u32 Bb = sbase + (bbuf ? SB1 : SB0);
        const u32 Bn = sbase + (bbuf ? SB0 : SB1);
        const char* nsrc = (kc + 1 < KC) ? bimg(kc + 1) : nullptr;

        for (int tap = 0; tap < 9; tap++) {
            const int s = g & 1;
            CP_WAIT0();
            __syncthreads();   // A[s] (and B chunks so far) visible; bufs s^1 free

            // prefetch next A tile
            {
                int ntap = tap + 1, nkc = kc;
                if (ntap == 9) { ntap = 0; nkc = kc + 1; }
                if (nkc < KC)
                    issueA((mtile * 9 + ntap) * KC + nkc, s ^ 1);
            }
            // prefetch 1/8 chunk of next-kc B during taps 0..7
            if (nsrc && tap < 8) {
                const u32 c0 = (u32)tap * 5184;
                for (u32 o = c0 + (u32)tid * 16; o < c0 + 5184; o += 4096)
                    cp16(Bn + o, nsrc + o);
            }
            CP_COMMIT();

            const int toff = (tap / 3 - 1) * 18 + (tap % 3 - 1);
            const u32 Ab = sbase + (u32)(s << 13);
#pragma unroll
            for (int q = 0; q < 4; q++) {
                const u32 ka = (u32)(q * 32) + akad;
                u32 a0[4], a1[4];
                ldm_x4(a0, Ab + ao0b + (ka ^ asz0));
                ldm_x4(a1, Ab + ao1b + (ka ^ asz1));
                const u32 kb = (u32)(q * 32) + bkad;
#pragma unroll
                for (int jj = 0; jj < 4; jj++) {
                    const int pr = pad00 + jj * 18 + toff;
                    const u32 bo = (u32)(pr * 128) + (kb ^ ((u32)(pr & 7) << 4));
                    u32 bh[4];
                    ldm_x4(bh, Bb + bo);
                    float* c0 = acc0 + jj * 8;
                    mma_f16(c0,     a0, bh[0], bh[1]);  mma_f16(c0 + 4, a0, bh[2], bh[3]);
                    float* c1 = acc1 + jj * 8;
                    mma_f16(c1,     a1, bh[0], bh[1]);  mma_f16(c1 + 4, a1, bh[2], bh[3]);
                }
            }
            g++;
        }
        bbuf ^= 1;
    }

    const int g2 = lane >> 2, qp = lane & 3;
#pragma unroll
    for (int mt = 0; mt < 2; mt++) {
        const float* am = mt ? acc1 : acc0;
        const int ocg0 = mtile * 64 + mrow + mt * 16 + g2;
        const int ocg1 = ocg0 + 8;
        const float bv0 = __ldg(bias + ocg0);
        const float bv1 = __ldg(bias + ocg1);
#pragma unroll
        for (int t = 0; t < 8; t++) {
            const int px = nbase + t * 8 + qp * 2;
            const float* c = am + t * 4;
            store2<OUTSEL>(ocg0, px, c[0] + bv0, c[1] + bv0, b, resid, pos_w, d_out);
            store2<OUTSEL>(ocg1, px, c[2] + bv1, c[3] + bv1, b, resid, pos_w, d_out);
        }
    }
}

// ---------------------------------------------------------------------------
// LSTM gate fusion (float4)
// ---------------------------------------------------------------------------
__global__ void __launch_bounds__(256)
gates_kernel(const float* __restrict__ c_cur, float* __restrict__ d_out)
{
    const u32 f = blockIdx.x * 256 + threadIdx.x;   // float4 index, < 1048576
    const int b  = (int)(f >> 13);                  // 8192 float4 per batch
    const int r4 = (int)(f & 8191);
    const float4* cc = (const float4*)(g_cc + (size_t)b * 640 * HW);
    const float4 ci = cc[r4];
    const float4 cf = cc[r4 + 8192];                // +128*HW floats
    const float4 cg = cc[r4 + 24576];               // +384*HW floats
    const float4 cu = ((const float4*)c_cur)[f];
    float4 o;
    o.x = sigmoidf_(cf.x) * cu.x + sigmoidf_(ci.x) * tanhf(cg.x);
    o.y = sigmoidf_(cf.y) * cu.y + sigmoidf_(ci.y) * tanhf(cg.y);
    o.z = sigmoidf_(cf.z) * cu.z + sigmoidf_(ci.z) * tanhf(cg.z);
    o.w = sigmoidf_(cf.w) * cu.w + sigmoidf_(ci.w) * tanhf(cg.w);
    ((float4*)(d_out + OFF_C))[f] = o;
}

// ---------------------------------------------------------------------------
// Fused attention: float4 k-pass, scalar v-pass, fp16-image output
// ---------------------------------------------------------------------------
__global__ void __launch_bounds__(256)
attn_fused(const float* __restrict__ concat_k, const float* __restrict__ concat_v,
           const unsigned int* __restrict__ mask,
           const float* __restrict__ pos_w, const float* __restrict__ pos_b,
           float* __restrict__ ret_k, float* __restrict__ ret_v)
{
    const int bh  = blockIdx.x;
    const int h   = bh & 7;
    const int tid = threadIdx.x;
    const int wid = tid >> 5, lane = tid & 31;

    // q as float4 (order-independent dot)
    float4 q4[4];
#pragma unroll
    for (int j = 0; j < 4; j++)
        q4[j] = ((const float4*)(g_q + (size_t)bh * DDIM))[j * 256 + tid];

    __shared__ float red2[8][MEM];
    __shared__ float w8[MEM];

    float part[MEM];
#pragma unroll
    for (int m = 0; m < MEM; m++) {
        const float4* ks = (const float4*)((m < 7)
            ? concat_k + ((size_t)bh * MEM + (m + 1)) * DDIM
            : ret_k    + ((size_t)bh * MEM + 7) * DDIM);   // slot 7 already has pos
        const float4* pw = (const float4*)(pos_w + (size_t)m * 32768 + (size_t)h * DDIM);
        float4* rk = (float4*)(ret_k + ((size_t)bh * MEM + m) * DDIM);
        float p = 0.0f;
#pragma unroll
        for (int j = 0; j < 4; j++) {
            const int f = j * 256 + tid;
            float4 kv = ks[f];
            if (m < 7) {
                const float4 pv = pw[f];
                kv.x += pv.x; kv.y += pv.y; kv.z += pv.z; kv.w += pv.w;
                rk[f] = kv;
            }
            p = fmaf(q4[j].x, kv.x, p);
            p = fmaf(q4[j].y, kv.y, p);
            p = fmaf(q4[j].z, kv.z, p);
            p = fmaf(q4[j].w, kv.w, p);
        }
        part[m] = p;
    }

#pragma unroll
    for (int m = 0; m < MEM; m++)
#pragma unroll
        for (int off = 16; off > 0; off >>= 1)
            part[m] += __shfl_down_sync(0xffffffffu, part[m], off);
    if (lane == 0)
#pragma unroll
        for (int m = 0; m < MEM; m++) red2[wid][m] = part[m];
    __syncthreads();

    if (tid == 0) {
        float sc[MEM];
        float mx = -1e30f;
#pragma unroll
        for (int m = 0; m < MEM; m++) {
            float t = 0.0f;
#pragma unroll
            for (int w = 0; w < 8; w++) t += red2[w][m];
            float mf = (m == 7) ? 3.0f : (mask[bh * MEM + m] != 0u ? -1e30f : 0.0f);
            sc[m] = mf + t + pos_b[m * NHEAD + h];
            mx = fmaxf(mx, sc[m]);
        }
        float ssum = 0.0f;
#pragma unroll
        for (int m = 0; m < MEM; m++) { sc[m] = expf(sc[m] - mx); ssum += sc[m]; }
        const float inv = 1.0f / ssum;
#pragma unroll
        for (int m = 0; m < MEM; m++) w8[m] = sc[m] * inv;
    }
    __syncthreads();

    float wl[MEM];
#pragma unroll
    for (int m = 0; m < MEM; m++) wl[m] = w8[m];

    // v-pass: (c, s) = (i, tid) mapping required for the fp16 image write
    float accv[16];
#pragma unroll
    for (int i = 0; i < 16; i++) {
        const int idx = i * 256 + tid;
        float acc = 0.0f;
#pragma unroll
        for (int m = 0; m < MEM; m++) {
            float vv;
            if (m < 7) {
                vv = concat_v[((size_t)bh * MEM + (m + 1)) * DDIM + idx];
                ret_v[((size_t)bh * MEM + m) * DDIM + idx] = vv;
            } else {
                vv = ret_v[((size_t)bh * MEM + 7) * DDIM + idx];
            }
            acc = fmaf(wl[m], vv, acc);
        }
        accv[i] = acc;
    }

    // write padded fp16 image for the out conv
    u32 ph[8];
#pragma unroll
    for (int j = 0; j < 8; j++) {
        const __half2 hh = __floats2half2_rn(accv[2*j], accv[2*j+1]);
        ph[j] = *(const u32*)&hh;
    }
    const int b  = bh >> 3;
    const int kc = h >> 2;
    char* dst = (char*)g_battn + (size_t)(b * 2 + kc) * BPAD_BYTES;
    const int padw = ((tid >> 4) + 1) * 18 + (tid & 15) + 1;
    const u32 rowb = (u32)(padw * 128);
    const u32 rswz = (u32)((padw & 7) << 4);
    const u32 coff = (u32)((h & 3) * 32);
    *(uint4*)(dst + rowb + ((coff +  0) ^ rswz)) = make_uint4(ph[0], ph[1], ph[2], ph[3]);
    *(uint4*)(dst + rowb + ((coff + 16) ^ rswz)) = make_uint4(ph[4], ph[5], ph[6], ph[7]);
}

// ---------------------------------------------------------------------------
// Fused LayerNorm + final LSTM update (float4)
// ---------------------------------------------------------------------------
__global__ void __launch_bounds__(512)
ln_final(const float* __restrict__ norm_w, const float* __restrict__ norm_b,
         float* __restrict__ d_out)
{
    const int b   = blockIdx.x;
    const int tid = threadIdx.x;
    const float4* p4 = (const float4*)(g_outp + (size_t)b * 32768);

    float s = 0.0f, s2 = 0.0f;
    for (int f = tid; f < 8192; f += 512) {
        const float4 v = p4[f];
        s += v.x + v.y + v.z + v.w;
        s2 = fmaf(v.x, v.x, s2); s2 = fmaf(v.y, v.y, s2);
        s2 = fmaf(v.z, v.z, s2); s2 = fmaf(v.w, v.w, s2);
    }
#pragma unroll
    for (int off = 16; off > 0; off >>= 1) {
        s  += __shfl_down_sync(0xffffffffu, s, off);
        s2 += __shfl_down_sync(0xffffffffu, s2, off);
    }
    __shared__ float rs_[16], rs2_[16];
    __shared__ float sh_mu, sh_rs;
    if ((tid & 31) == 0) { rs_[tid >> 5] = s; rs2_[tid >> 5] = s2; }
    __syncthreads();
    if (tid == 0) {
        float ts = 0.0f, ts2 = 0.0f;
#pragma unroll
        for (int w = 0; w < 16; w++) { ts += rs_[w]; ts2 += rs2_[w]; }
        const float mu  = ts * (1.0f / 32768.0f);
        const float var = ts2 * (1.0f / 32768.0f) - mu * mu;
        sh_mu = mu;
        sh_rs = rsqrtf(var + 1e-5f);
    }
    __syncthreads();

    const float mu = sh_mu, rs = sh_rs;
    const float4* cc4 = (const float4*)(g_cc + (size_t)b * 640 * HW);
    const float4* nw4 = (const float4*)norm_w;
    const float4* nb4 = (const float4*)norm_b;
    float4* dc = (float4*)(d_out + OFF_C + (size_t)b * 32768);
    float4* dh = (float4*)(d_out + OFF_H + (size_t)b * 32768);
    for (int f = tid; f < 8192; f += 512) {
        const float4 pv = p4[f];
        const float4 wv = nw4[f], bv = nb4[f];
        const float4 ov = cc4[f + 16384];   // +256*HW floats
        const float4 av = cc4[f + 32768];   // +512*HW floats
        float4 cv = dc[f];
        float4 hv;
        {
            const float ln = (pv.x - mu) * rs * wv.x + bv.x;
            cv.x += sigmoidf_(av.x) * tanhf(ln);
            hv.x = sigmoidf_(ov.x) * tanhf(cv.x);
        }
        {
            const float ln = (pv.y - mu) * rs * wv.y + bv.y;
            cv.y += sigmoidf_(av.y) * tanhf(ln);
            hv.y = sigmoidf_(ov.y) * tanhf(cv.y);
        }
        {
            const float ln = (pv.z - mu) * rs * wv.z + bv.z;
            cv.z += sigmoidf_(av.z) * tanhf(ln);
            hv.z = sigmoidf_(ov.z) * tanhf(cv.z);
        }
        {
            const float ln = (pv.w - mu) * rs * wv.w + bv.w;
            cv.w += sigmoidf_(av.w) * tanhf(ln);
            hv.w = sigmoidf_(ov.w) * tanhf(cv.w);
        }
        dc[f] = cv;
        dh[f] = hv;
    }
}

// ---------------------------------------------------------------------------
// Launch — prep_in, then two-stream fork/join
// ---------------------------------------------------------------------------
extern "C" void kernel_launch(void* const* d_in, const int* in_sizes, int n_in,
                              void* d_out_v, int out_size)
{
    const float* input    = (const float*)d_in[0];
    const float* h_cur    = (const float*)d_in[1];
    const float* c_cur    = (const float*)d_in[2];
    const float* concat_k = (const float*)d_in[3];
    const float* concat_v = (const float*)d_in[4];
    const unsigned int* attn_mask = (const unsigned int*)d_in[5];
    const float* main_w   = (const float*)d_in[6];
    const float* main_b   = (const float*)d_in[7];
    const float* proj_w   = (const float*)d_in[8];
    const float* proj_b   = (const float*)d_in[9];
    const float* out_w    = (const float*)d_in[10];
    const float* out_b    = (const float*)d_in[11];
    const float* norm_w   = (const float*)d_in[12];
    const float* norm_b   = (const float*)d_in[13];
    const float* pos_w    = (const float*)d_in[14];
    const float* pos_b    = (const float*)d_in[15];
    float* d_out = (float*)d_out_v;

    cudaFuncSetAttribute(conv_mma<4,0>, cudaFuncAttributeMaxDynamicSharedMemorySize, CONV_SMEM);
    cudaFuncSetAttribute(conv_mma<2,1>, cudaFuncAttributeMaxDynamicSharedMemorySize, CONV_SMEM);
    cudaFuncSetAttribute(conv_mma<2,2>, cudaFuncAttributeMaxDynamicSharedMemorySize, CONV_SMEM);

    __half *wm, *wp, *wo;
    char *bin_p, *battn_p;
    cudaGetSymbolAddress((void**)&wm, g_wm);
    cudaGetSymbolAddress((void**)&wp, g_wp);
    cudaGetSymbolAddress((void**)&wo, g_wo);
    cudaGetSymbolAddress((void**)&bin_p, g_bin);
    cudaGetSymbolAddress((void**)&battn_p, g_battn);

    cudaStream_t s0 = 0;
    cudaStream_t sB = g_res.sB;

    // ---- shared input prep (needed by main + proj) ----
    prep_in<<<dim3(4, BATCH), 256, 0, s0>>>(input, h_cur);

    // ---- fork ----
    cudaEventRecord(g_res.evFork, s0);
    cudaStreamWaitEvent(sB, g_res.evFork, 0);

    // ---- chain B (sB): proj weights+conv -> attn -> out conv ----
    prep_w<1><<<(108 * 2048) / 256, 256, 0, sB>>>(proj_w, 108, 2);
    prep_w<2><<<( 36 * 2048) / 256, 256, 0, sB>>>(out_w,   36, 2);
    conv_mma<2,1><<<dim3(6, BATCH), 256, CONV_SMEM, sB>>>(
        wp, bin_p, 4, proj_b, nullptr, pos_w, d_out);
    attn_fused<<<BH, 256, 0, sB>>>(concat_k, concat_v, attn_mask, pos_w, pos_b,
                                   d_out + OFF_K, d_out + OFF_V);
    conv_mma<2,2><<<dim3(2, BATCH), 256, CONV_SMEM, sB>>>(
        wo, battn_p, 2, out_b, input, nullptr, d_out);

    // ---- chain A (s0): main weights+conv -> gates ----
    prep_w<0><<<(360 * 2048) / 256, 256, 0, s0>>>(main_w, 360, 4);
    conv_mma<4,0><<<dim3(10, BATCH), 256, CONV_SMEM, s0>>>(
        wm, bin_p, 4, main_b, nullptr, nullptr, d_out);
    gates_kernel<<<4096, 256, 0, s0>>>(c_cur, d_out);

    // ---- join ----
    cudaEventRecord(g_res.evJoin, sB);
    cudaStreamWaitEvent(s0, g_res.evJoin, 0);

    // ---- final fused LayerNorm + LSTM update ----
    ln_final<<<BATCH, 512, 0, s0>>>(norm_w, norm_b, d_out);
}